// round 14
// baseline (speedup 1.0000x reference)
#include <cuda_runtime.h>
#include <cuda_bf16.h>
#include <cstdint>

#define N_NODES 100000
#define E_MAX   1600000
#define FDIM 512
#define HDIM 64

// ---------------- scratch ----------------
__device__ __align__(128) float g_x1g[(size_t)N_NODES * HDIM];   // X@W1 (UNscaled)
__device__ __align__(128) float g_hs[(size_t)N_NODES * HDIM];    // relu(agg1*nd)*ns
__device__ __align__(128) unsigned short g_a2h[(size_t)N_NODES * HDIM];
__device__ __align__(128) unsigned short g_a2l[(size_t)N_NODES * HDIM];
__device__ __align__(128) float g_norm_src[N_NODES];
__device__ __align__(128) float g_norm_dst[N_NODES];
__device__ __align__(128) unsigned short g_w1ht[HDIM * FDIM];
__device__ __align__(128) unsigned short g_w1lt[HDIM * FDIM];
__device__ __align__(128) unsigned short g_w2ht[FDIM * HDIM];
__device__ __align__(128) unsigned short g_w2lt[FDIM * HDIM];
__device__ int g_cnt_in[N_NODES];
__device__ int g_cnt_out[N_NODES];
__device__ int g_row_start[N_NODES + 1];
__device__ int g_cursor[N_NODES];
__device__ int g_esrc[E_MAX];
__device__ int g_bsum[256];
__device__ int g_is64;

// ---------------- helpers ----------------
__device__ __forceinline__ uint32_t smem_to_u32(const void* p) {
    uint32_t a;
    asm("{ .reg .u64 t; cvta.to.shared.u64 t, %1; cvt.u32.u64 %0, t; }" : "=r"(a) : "l"(p));
    return a;
}
__device__ __forceinline__ void ldsm4(uint32_t* r, uint32_t addr) {
    asm volatile("ldmatrix.sync.aligned.m8n8.x4.shared.b16 {%0,%1,%2,%3}, [%4];"
                 : "=r"(r[0]), "=r"(r[1]), "=r"(r[2]), "=r"(r[3]) : "r"(addr));
}
__device__ __forceinline__ void mma_bf16(float* c, const uint32_t* a, const uint32_t* b) {
    asm volatile(
        "mma.sync.aligned.m16n8k16.row.col.f32.bf16.bf16.f32 "
        "{%0,%1,%2,%3}, {%4,%5,%6,%7}, {%8,%9}, {%0,%1,%2,%3};"
        : "+f"(c[0]), "+f"(c[1]), "+f"(c[2]), "+f"(c[3])
        : "r"(a[0]), "r"(a[1]), "r"(a[2]), "r"(a[3]), "r"(b[0]), "r"(b[1]));
}
__device__ __forceinline__ void split2(float x, float y, uint32_t& h2, uint32_t& l2) {
    __nv_bfloat162 bh = __floats2bfloat162_rn(x, y);
    float2 f = __bfloat1622float2(bh);
    __nv_bfloat162 bl = __floats2bfloat162_rn(x - f.x, y - f.y);
    h2 = reinterpret_cast<uint32_t&>(bh);
    l2 = reinterpret_cast<uint32_t&>(bl);
}
__device__ __forceinline__ void bf16split(float x, unsigned short& h, unsigned short& l) {
    __nv_bfloat16 bh = __float2bfloat16(x);
    float fh = __bfloat162float(bh);
    __nv_bfloat16 bl = __float2bfloat16(x - fh);
    h = __bfloat16_as_ushort(bh);
    l = __bfloat16_as_ushort(bl);
}
__device__ __forceinline__ int load_idx(const void* p, int e, int is64) {
    if (is64) return (int)__ldg(reinterpret_cast<const long long*>(p) + e);
    return __ldg(reinterpret_cast<const int*>(p) + e);
}

// ---------------- zero counters + index width probe (fused) ----------------
__global__ __launch_bounds__(256) void zero_counts_kernel(const int* __restrict__ src32,
                                                          const int* __restrict__ dst32,
                                                          int n, int E) {
    int i = blockIdx.x * blockDim.x + threadIdx.x;
    if (i < n) { g_cnt_in[i] = 0; g_cnt_out[i] = 0; }
    if (i == 0) {
        int m = E < 256 ? E : 256;
        int is64 = 1;
        for (int k = 0; k < m; k++) {
            if (src32[2 * k + 1] != 0 || dst32[2 * k + 1] != 0) { is64 = 0; break; }
        }
        g_is64 = is64;
    }
}

// ---------------- weight pre-conversion ----------------
__global__ __launch_bounds__(256) void wconv_kernel(const float* __restrict__ W1,
                                                    const float* __restrict__ W2) {
    int i = blockIdx.x * blockDim.x + threadIdx.x;
    if (i < FDIM * HDIM) {
        unsigned short h, l;
        {
            int k = i >> 6, n = i & 63;
            bf16split(__ldg(&W1[i]), h, l);
            g_w1ht[n * FDIM + k] = h;
            g_w1lt[n * FDIM + k] = l;
        }
        {
            int k = i >> 9, n = i & 511;
            bf16split(__ldg(&W2[i]), h, l);
            g_w2ht[n * HDIM + k] = h;
            g_w2lt[n * HDIM + k] = l;
        }
    }
}

// ---------------- graph build ----------------
__global__ __launch_bounds__(256) void hist_kernel(const void* __restrict__ src,
                                                   const void* __restrict__ dst, int E) {
    int e = blockIdx.x * blockDim.x + threadIdx.x;
    if (e < E) {
        int is64 = g_is64;
        atomicAdd(&g_cnt_out[load_idx(src, e, is64)], 1);
        atomicAdd(&g_cnt_in[load_idx(dst, e, is64)], 1);
    }
}
__global__ __launch_bounds__(256) void scan1_kernel(int n) {
    __shared__ int sh[256];
    int tid = threadIdx.x;
    int base = blockIdx.x * 1024 + tid * 4;
    int v[4];
#pragma unroll
    for (int k = 0; k < 4; k++) v[k] = (base + k < n) ? g_cnt_in[base + k] : 0;
    int t = v[0] + v[1] + v[2] + v[3];
    sh[tid] = t;
    __syncthreads();
    for (int off = 1; off < 256; off <<= 1) {
        int x = (tid >= off) ? sh[tid - off] : 0;
        __syncthreads();
        sh[tid] += x;
        __syncthreads();
    }
    int run = sh[tid] - t;
#pragma unroll
    for (int k = 0; k < 4; k++) {
        if (base + k < n) g_row_start[base + k] = run;
        run += v[k];
    }
    if (tid == 255) g_bsum[blockIdx.x] = sh[255];
}
__global__ void scan2_kernel(int nb) {
    __shared__ int sh[256];
    int t = threadIdx.x;
    int v = (t < nb) ? g_bsum[t] : 0;
    sh[t] = v;
    __syncthreads();
    for (int off = 1; off < 256; off <<= 1) {
        int x = (t >= off) ? sh[t - off] : 0;
        __syncthreads();
        sh[t] += x;
        __syncthreads();
    }
    if (t < nb) g_bsum[t] = sh[t] - v;
}
__global__ __launch_bounds__(256) void scan3_kernel(int n, int E) {
    int i = blockIdx.x * blockDim.x + threadIdx.x;
    if (i < n) {
        int v = g_row_start[i] + g_bsum[i >> 10];
        g_row_start[i] = v;
        g_cursor[i] = v;
        g_norm_src[i] = rsqrtf(fmaxf((float)g_cnt_out[i], 1.0f));
        g_norm_dst[i] = rsqrtf(fmaxf((float)g_cnt_in[i], 1.0f));
    }
    if (i == 0) g_row_start[n] = E;
}
__global__ __launch_bounds__(256) void fill_kernel(const void* __restrict__ src,
                                                   const void* __restrict__ dst, int E) {
    int e = blockIdx.x * blockDim.x + threadIdx.x;
    if (e < E) {
        int is64 = g_is64;
        int s = load_idx(src, e, is64);
        int d = load_idx(dst, e, is64);
        int pos = atomicAdd(&g_cursor[d], 1);
        g_esrc[pos] = s;
    }
}

// ---------------- aggregation (CSR, atomic-free, MLP-4) ----------------
// MODE 0: msg is UNscaled X@W1: out = relu((sum ns[sa]*msg[sa]) * nd) * ns (fp32)
// MODE 1: msg fully scaled: out = (sum msg[sa]) * nd, bf16 hi/lo split
template <int MODE>
__global__ __launch_bounds__(256) void agg_kernel(const float* __restrict__ msg,
                                                  float* __restrict__ outf,
                                                  unsigned short* __restrict__ outh,
                                                  unsigned short* __restrict__ outl,
                                                  int n) {
    int node = blockIdx.x * 16 + (threadIdx.x >> 4);
    int c = threadIdx.x & 15;
    if (node >= n) return;
    int j = g_row_start[node];
    int s1 = g_row_start[node + 1];
    float4 acc = make_float4(0.f, 0.f, 0.f, 0.f);
    for (; j + 3 < s1; j += 4) {
        int sa = __ldg(&g_esrc[j]);
        int sb = __ldg(&g_esrc[j + 1]);
        int sc = __ldg(&g_esrc[j + 2]);
        int sd = __ldg(&g_esrc[j + 3]);
        float4 va = __ldg(reinterpret_cast<const float4*>(msg + (size_t)sa * HDIM + c * 4));
        float4 vb = __ldg(reinterpret_cast<const float4*>(msg + (size_t)sb * HDIM + c * 4));
        float4 vc = __ldg(reinterpret_cast<const float4*>(msg + (size_t)sc * HDIM + c * 4));
        float4 vd = __ldg(reinterpret_cast<const float4*>(msg + (size_t)sd * HDIM + c * 4));
        if (MODE == 0) {
            float na = __ldg(&g_norm_src[sa]);
            float nb = __ldg(&g_norm_src[sb]);
            float nc = __ldg(&g_norm_src[sc]);
            float ndd = __ldg(&g_norm_src[sd]);
            acc.x = fmaf(va.x, na, acc.x); acc.y = fmaf(va.y, na, acc.y);
            acc.z = fmaf(va.z, na, acc.z); acc.w = fmaf(va.w, na, acc.w);
            acc.x = fmaf(vb.x, nb, acc.x); acc.y = fmaf(vb.y, nb, acc.y);
            acc.z = fmaf(vb.z, nb, acc.z); acc.w = fmaf(vb.w, nb, acc.w);
            acc.x = fmaf(vc.x, nc, acc.x); acc.y = fmaf(vc.y, nc, acc.y);
            acc.z = fmaf(vc.z, nc, acc.z); acc.w = fmaf(vc.w, nc, acc.w);
            acc.x = fmaf(vd.x, ndd, acc.x); acc.y = fmaf(vd.y, ndd, acc.y);
            acc.z = fmaf(vd.z, ndd, acc.z); acc.w = fmaf(vd.w, ndd, acc.w);
        } else {
            acc.x += va.x + vb.x + vc.x + vd.x;
            acc.y += va.y + vb.y + vc.y + vd.y;
            acc.z += va.z + vb.z + vc.z + vd.z;
            acc.w += va.w + vb.w + vc.w + vd.w;
        }
    }
    for (; j < s1; j++) {
        int sa = __ldg(&g_esrc[j]);
        float4 va = __ldg(reinterpret_cast<const float4*>(msg + (size_t)sa * HDIM + c * 4));
        if (MODE == 0) {
            float na = __ldg(&g_norm_src[sa]);
            acc.x = fmaf(va.x, na, acc.x); acc.y = fmaf(va.y, na, acc.y);
            acc.z = fmaf(va.z, na, acc.z); acc.w = fmaf(va.w, na, acc.w);
        } else {
            acc.x += va.x; acc.y += va.y; acc.z += va.z; acc.w += va.w;
        }
    }
    float nd = g_norm_dst[node];
    if (MODE == 0) {
        float ns = g_norm_src[node];
        float4 o;
        o.x = fmaxf(acc.x * nd, 0.f) * ns;
        o.y = fmaxf(acc.y * nd, 0.f) * ns;
        o.z = fmaxf(acc.z * nd, 0.f) * ns;
        o.w = fmaxf(acc.w * nd, 0.f) * ns;
        reinterpret_cast<float4*>(outf)[(size_t)node * 16 + c] = o;
    } else {
        uint32_t h01, l01, h23, l23;
        split2(acc.x * nd, acc.y * nd, h01, l01);
        split2(acc.z * nd, acc.w * nd, h23, l23);
        size_t off = ((size_t)node * HDIM + c * 4) >> 2;
        reinterpret_cast<uint2*>(outh)[off] = make_uint2(h01, h23);
        reinterpret_cast<uint2*>(outl)[off] = make_uint2(l01, l23);
    }
}

// ---------------- GEMM1: C[M,64] = A(fp32)[M,512] @ W1 (UNscaled output) ----------------
// m0 = m-tile offset (dual-stream split).
#define AST 40
__global__ __launch_bounds__(256) void gemm1_kernel(const float* __restrict__ A,
                                                    const unsigned short* __restrict__ Bth,
                                                    const unsigned short* __restrict__ Btl,
                                                    float* __restrict__ C, int M, int m0) {
    __shared__ __align__(16) unsigned short sAh[128 * AST];
    __shared__ __align__(16) unsigned short sAl[128 * AST];
    __shared__ __align__(16) unsigned short sBh[64 * AST];
    __shared__ __align__(16) unsigned short sBl[64 * AST];

    const int tid = threadIdx.x;
    const int wid = tid >> 5, lid = tid & 31;
    const int wm = wid & 3, wn = wid >> 2;
    const int block_m = (m0 + blockIdx.x) * 128;

    float acc[2][4][4];
#pragma unroll
    for (int i = 0; i < 2; i++)
#pragma unroll
        for (int j = 0; j < 4; j++)
#pragma unroll
            for (int q = 0; q < 4; q++) acc[i][j][q] = 0.f;

    const uint32_t aH = smem_to_u32(sAh);
    const uint32_t aL = smem_to_u32(sAl);
    const uint32_t bH = smem_to_u32(sBh);
    const uint32_t bL = smem_to_u32(sBl);

    const int b_n = tid >> 2, b_k8 = (tid & 3) * 8;
    for (int k0 = 0; k0 < FDIM; k0 += 32) {
#pragma unroll
        for (int it = 0; it < 4; it++) {
            int f = it * 256 + tid;
            int r = f >> 3, c4 = f & 7;
            int gr = block_m + r;
            float4 v = make_float4(0.f, 0.f, 0.f, 0.f);
            if (gr < M)
                v = __ldg(reinterpret_cast<const float4*>(A + (size_t)gr * FDIM + k0 + c4 * 4));
            uint32_t h01, l01, h23, l23;
            split2(v.x, v.y, h01, l01);
            split2(v.z, v.w, h23, l23);
            *reinterpret_cast<uint2*>(&sAh[r * AST + c4 * 4]) = make_uint2(h01, h23);
            *reinterpret_cast<uint2*>(&sAl[r * AST + c4 * 4]) = make_uint2(l01, l23);
        }
        {
            const size_t go = (size_t)b_n * FDIM + k0 + b_k8;
            uint4 vh = __ldg(reinterpret_cast<const uint4*>(Bth + go));
            uint4 vl = __ldg(reinterpret_cast<const uint4*>(Btl + go));
            *reinterpret_cast<uint4*>(&sBh[b_n * AST + b_k8]) = vh;
            *reinterpret_cast<uint4*>(&sBl[b_n * AST + b_k8]) = vl;
        }
        __syncthreads();

#pragma unroll
        for (int ks = 0; ks < 32; ks += 16) {
            uint32_t ah[2][4], al[2][4], bh[4][2], bl[4][2];
#pragma unroll
            for (int mf = 0; mf < 2; mf++) {
                uint32_t rowA = wm * 32 + mf * 16 + (lid & 15);
                uint32_t off = (rowA * AST + ks + (lid >> 4) * 8) * 2;
                ldsm4(ah[mf], aH + off);
                ldsm4(al[mf], aL + off);
            }
#pragma unroll
            for (int p = 0; p < 2; p++) {
                uint32_t nrow = wn * 32 + p * 16 + ((lid >> 4) & 1) * 8 + (lid & 7);
                uint32_t off = (nrow * AST + ks + ((lid >> 3) & 1) * 8) * 2;
                uint32_t r[4];
                ldsm4(r, bH + off);
                bh[2 * p][0] = r[0]; bh[2 * p][1] = r[1];
                bh[2 * p + 1][0] = r[2]; bh[2 * p + 1][1] = r[3];
                ldsm4(r, bL + off);
                bl[2 * p][0] = r[0]; bl[2 * p][1] = r[1];
                bl[2 * p + 1][0] = r[2]; bl[2 * p + 1][1] = r[3];
            }
#pragma unroll
            for (int mf = 0; mf < 2; mf++)
#pragma unroll
                for (int nf = 0; nf < 4; nf++) {
                    mma_bf16(acc[mf][nf], ah[mf], bh[nf]);
                    mma_bf16(acc[mf][nf], ah[mf], bl[nf]);
                    mma_bf16(acc[mf][nf], al[mf], bh[nf]);
                }
        }
        __syncthreads();
    }

    int lrow = lid >> 2, lcol = (lid & 3) * 2;
#pragma unroll
    for (int mf = 0; mf < 2; mf++)
#pragma unroll
        for (int half = 0; half < 2; half++) {
            int row = block_m + wm * 32 + mf * 16 + lrow + half * 8;
            if (row < M) {
#pragma unroll
                for (int nf = 0; nf < 4; nf++) {
                    int col = wn * 32 + nf * 8 + lcol;
                    float2 o = make_float2(acc[mf][nf][half * 2],
                                           acc[mf][nf][half * 2 + 1]);
                    *reinterpret_cast<float2*>(C + (size_t)row * HDIM + col) = o;
                }
            }
        }
}

// ---------------- GEMM2: C[M,512] = A(pre-split bf16)[M,64] @ W2 ----------------
#define AST2 72
#define G2_SMEM (2 * 128 * AST2 * 2 + 2 * 64 * AST2 * 2)
__global__ __launch_bounds__(256) void gemm2_kernel(const unsigned short* __restrict__ Ah,
                                                    const unsigned short* __restrict__ Al,
                                                    const unsigned short* __restrict__ Bth,
                                                    const unsigned short* __restrict__ Btl,
                                                    float* __restrict__ C, int M) {
    extern __shared__ __align__(16) unsigned short dyn[];
    unsigned short* sAh = dyn;
    unsigned short* sAl = sAh + 128 * AST2;
    unsigned short* sBh = sAl + 128 * AST2;
    unsigned short* sBl = sBh + 64 * AST2;

    const int tid = threadIdx.x;
    const int wid = tid >> 5, lid = tid & 31;
    const int wm = wid & 3, wn = wid >> 2;
    const int block_m = blockIdx.x * 128;

    const uint32_t aH = smem_to_u32(sAh);
    const uint32_t aL = smem_to_u32(sAl);
    const uint32_t bH = smem_to_u32(sBh);
    const uint32_t bL = smem_to_u32(sBl);

#pragma unroll
    for (int it = 0; it < 4; it++) {
        int u = it * 256 + tid;
        int r = u >> 3, q8 = (u & 7) * 8;
        int gr = block_m + r;
        uint4 vh = make_uint4(0, 0, 0, 0), vl = make_uint4(0, 0, 0, 0);
        if (gr < M) {
            size_t go = (size_t)gr * HDIM + q8;
            vh = __ldg(reinterpret_cast<const uint4*>(Ah + go));
            vl = __ldg(reinterpret_cast<const uint4*>(Al + go));
        }
        *reinterpret_cast<uint4*>(&sAh[r * AST2 + q8]) = vh;
        *reinterpret_cast<uint4*>(&sAl[r * AST2 + q8]) = vl;
    }

    int lrow = lid >> 2, lcol = (lid & 3) * 2;

    for (int nt = 0; nt < FDIM / 64; nt++) {
        const int n0 = nt * 64;
        __syncthreads();
#pragma unroll
        for (int it = 0; it < 2; it++) {
            int u = it * 256 + tid;
            int r = u >> 3, q8 = (u & 7) * 8;
            size_t go = (size_t)(n0 + r) * HDIM + q8;
            uint4 vh = __ldg(reinterpret_cast<const uint4*>(Bth + go));
            uint4 vl = __ldg(reinterpret_cast<const uint4*>(Btl + go));
            *reinterpret_cast<uint4*>(&sBh[r * AST2 + q8]) = vh;
            *reinterpret_cast<uint4*>(&sBl[r * AST2 + q8]) = vl;
        }
        __syncthreads();

        float acc[2][4][4];
#pragma unroll
        for (int i = 0; i < 2; i++)
#pragma unroll
            for (int j = 0; j < 4; j++)
#pragma unroll
                for (int q = 0; q < 4; q++) acc[i][j][q] = 0.f;

#pragma unroll
        for (int ks = 0; ks < 64; ks += 16) {
            uint32_t ah[2][4], al[2][4], bh[4][2], bl[4][2];
#pragma unroll
            for (int mf = 0; mf < 2; mf++) {
                uint32_t rowA = wm * 32 + mf * 16 + (lid & 15);
                uint32_t off = (rowA * AST2 + ks + (lid >> 4) * 8) * 2;
                ldsm4(ah[mf], aH + off);
                ldsm4(al[mf], aL + off);
            }
#pragma unroll
            for (int p = 0; p < 2; p++) {
                uint32_t nrow = wn * 32 + p * 16 + ((lid >> 4) & 1) * 8 + (lid & 7);
                uint32_t off = (nrow * AST2 + ks + ((lid >> 3) & 1) * 8) * 2;
                uint32_t r[4];
                ldsm4(r, bH + off);
                bh[2 * p][0] = r[0]; bh[2 * p][1] = r[1];
                bh[2 * p + 1][0] = r[2]; bh[2 * p + 1][1] = r[3];
                ldsm4(r, bL + off);
                bl[2 * p][0] = r[0]; bl[2 * p][1] = r[1];
                bl[2 * p + 1][0] = r[2]; bl[2 * p + 1][1] = r[3];
            }
#pragma unroll
            for (int mf = 0; mf < 2; mf++)
#pragma unroll
                for (int nf = 0; nf < 4; nf++) {
                    mma_bf16(acc[mf][nf], ah[mf], bh[nf]);
                    mma_bf16(acc[mf][nf], ah[mf], bl[nf]);
                    mma_bf16(acc[mf][nf], al[mf], bh[nf]);
                }
        }

#pragma unroll
        for (int mf = 0; mf < 2; mf++)
#pragma unroll
            for (int half = 0; half < 2; half++) {
                int row = block_m + wm * 32 + mf * 16 + lrow + half * 8;
                if (row < M) {
#pragma unroll
                    for (int nf = 0; nf < 4; nf++) {
                        int col = n0 + wn * 32 + nf * 8 + lcol;
                        float2 o = make_float2(acc[mf][nf][half * 2],
                                               acc[mf][nf][half * 2 + 1]);
                        *reinterpret_cast<float2*>(C + (size_t)row * FDIM + col) = o;
                    }
                }
            }
    }
}

// ---------------- streams/events (created once) ----------------
static cudaStream_t g_s2;
static cudaEvent_t g_evF, g_evW, g_evJ;
static struct StreamInit {
    StreamInit() {
        cudaStreamCreateWithFlags(&g_s2, cudaStreamNonBlocking);
        cudaEventCreateWithFlags(&g_evF, cudaEventDisableTiming);
        cudaEventCreateWithFlags(&g_evW, cudaEventDisableTiming);
        cudaEventCreateWithFlags(&g_evJ, cudaEventDisableTiming);
    }
} g_stream_init;

// ---------------- launch ----------------
extern "C" void kernel_launch(void* const* d_in, const int* in_sizes, int n_in,
                              void* d_out, int out_size) {
    const float* features = (const float*)d_in[0];
    const void* src = d_in[1];
    const void* dst = d_in[2];
    const float* W1 = (const float*)d_in[3];
    const float* W2 = (const float*)d_in[4];
    float* out = (float*)d_out;

    const int N = N_NODES;
    const int E = in_sizes[1];

    float *p_x1g, *p_hs;
    unsigned short *p_a2h, *p_a2l, *p_w1ht, *p_w1lt, *p_w2ht, *p_w2lt;
    cudaGetSymbolAddress((void**)&p_x1g, g_x1g);
    cudaGetSymbolAddress((void**)&p_hs, g_hs);
    cudaGetSymbolAddress((void**)&p_a2h, g_a2h);
    cudaGetSymbolAddress((void**)&p_a2l, g_a2l);
    cudaGetSymbolAddress((void**)&p_w1ht, g_w1ht);
    cudaGetSymbolAddress((void**)&p_w1lt, g_w1lt);
    cudaGetSymbolAddress((void**)&p_w2ht, g_w2ht);
    cudaGetSymbolAddress((void**)&p_w2lt, g_w2lt);

    cudaFuncSetAttribute(gemm2_kernel, cudaFuncAttributeMaxDynamicSharedMemorySize, G2_SMEM);

    const int nb_scan = (N + 1023) / 1024;
    const int mtiles = (N + 127) / 128;
    const int mtiles_side = (mtiles * 4) / 5;          // ~80% on side stream
    const int mtiles_main = mtiles - mtiles_side;

    // ---- fork: wconv + 80% of GEMM1 on side stream ----
    cudaEventRecord(g_evF, 0);
    cudaStreamWaitEvent(g_s2, g_evF, 0);
    wconv_kernel<<<(FDIM * HDIM + 255) / 256, 256, 0, g_s2>>>(W1, W2);
    cudaEventRecord(g_evW, g_s2);
    gemm1_kernel<<<mtiles_side, 256, 0, g_s2>>>(features, p_w1ht, p_w1lt, p_x1g, N, 0);
    cudaEventRecord(g_evJ, g_s2);

    // ---- main stream: graph build, then the remaining 20% of GEMM1 ----
    zero_counts_kernel<<<(N + 255) / 256, 256>>>((const int*)src, (const int*)dst, N, E);
    hist_kernel<<<(E + 255) / 256, 256>>>(src, dst, E);
    scan1_kernel<<<nb_scan, 256>>>(N);
    scan2_kernel<<<1, 256>>>(nb_scan);
    scan3_kernel<<<(N + 255) / 256, 256>>>(N, E);
    fill_kernel<<<(E + 255) / 256, 256>>>(src, dst, E);
    cudaStreamWaitEvent(0, g_evW, 0);  // weights ready (long past by now)
    gemm1_kernel<<<mtiles_main, 256>>>(features, p_w1ht, p_w1lt, p_x1g, N, mtiles_side);

    // ---- join, then tail ----
    cudaStreamWaitEvent(0, g_evJ, 0);
    agg_kernel<0><<<(N + 15) / 16, 256>>>(p_x1g, p_hs, nullptr, nullptr, N);
    agg_kernel<1><<<(N + 15) / 16, 256>>>(p_hs, nullptr, p_a2h, p_a2l, N);
    gemm2_kernel<<<mtiles, 256, G2_SMEM>>>(p_a2h, p_a2l, p_w2ht, p_w2lt, out, N);
}

// round 15
// speedup vs baseline: 1.1900x; 1.1900x over previous
#include <cuda_runtime.h>
#include <cuda_bf16.h>
#include <cuda_fp16.h>
#include <cstdint>

#define N_NODES 100000
#define E_MAX   1600000
#define FDIM 512
#define HDIM 64

// ---------------- scratch ----------------
__device__ __align__(128) __half g_x1g[(size_t)N_NODES * HDIM];  // X@W1 (UNscaled, fp16)
__device__ __align__(128) __half g_hs[(size_t)N_NODES * HDIM];   // relu(agg1*nd)*ns (fp16)
__device__ __align__(128) unsigned short g_a2h[(size_t)N_NODES * HDIM];
__device__ __align__(128) unsigned short g_a2l[(size_t)N_NODES * HDIM];
__device__ __align__(128) float g_norm_src[N_NODES];
__device__ __align__(128) float g_norm_dst[N_NODES];
__device__ __align__(128) unsigned short g_w1ht[HDIM * FDIM];
__device__ __align__(128) unsigned short g_w1lt[HDIM * FDIM];
__device__ __align__(128) unsigned short g_w2ht[FDIM * HDIM];
__device__ __align__(128) unsigned short g_w2lt[FDIM * HDIM];
__device__ int g_cnt_in[N_NODES];
__device__ int g_cnt_out[N_NODES];
__device__ int g_row_start[N_NODES + 1];
__device__ int g_cursor[N_NODES];
__device__ int g_esrc[E_MAX];
__device__ int g_bsum[256];
__device__ int g_is64;

// ---------------- helpers ----------------
__device__ __forceinline__ uint32_t smem_to_u32(const void* p) {
    uint32_t a;
    asm("{ .reg .u64 t; cvta.to.shared.u64 t, %1; cvt.u32.u64 %0, t; }" : "=r"(a) : "l"(p));
    return a;
}
__device__ __forceinline__ void ldsm4(uint32_t* r, uint32_t addr) {
    asm volatile("ldmatrix.sync.aligned.m8n8.x4.shared.b16 {%0,%1,%2,%3}, [%4];"
                 : "=r"(r[0]), "=r"(r[1]), "=r"(r[2]), "=r"(r[3]) : "r"(addr));
}
__device__ __forceinline__ void mma_bf16(float* c, const uint32_t* a, const uint32_t* b) {
    asm volatile(
        "mma.sync.aligned.m16n8k16.row.col.f32.bf16.bf16.f32 "
        "{%0,%1,%2,%3}, {%4,%5,%6,%7}, {%8,%9}, {%0,%1,%2,%3};"
        : "+f"(c[0]), "+f"(c[1]), "+f"(c[2]), "+f"(c[3])
        : "r"(a[0]), "r"(a[1]), "r"(a[2]), "r"(a[3]), "r"(b[0]), "r"(b[1]));
}
__device__ __forceinline__ void split2(float x, float y, uint32_t& h2, uint32_t& l2) {
    __nv_bfloat162 bh = __floats2bfloat162_rn(x, y);
    float2 f = __bfloat1622float2(bh);
    __nv_bfloat162 bl = __floats2bfloat162_rn(x - f.x, y - f.y);
    h2 = reinterpret_cast<uint32_t&>(bh);
    l2 = reinterpret_cast<uint32_t&>(bl);
}
__device__ __forceinline__ void bf16split(float x, unsigned short& h, unsigned short& l) {
    __nv_bfloat16 bh = __float2bfloat16(x);
    float fh = __bfloat162float(bh);
    __nv_bfloat16 bl = __float2bfloat16(x - fh);
    h = __bfloat16_as_ushort(bh);
    l = __bfloat16_as_ushort(bl);
}
__device__ __forceinline__ int load_idx(const void* p, int e, int is64) {
    if (is64) return (int)__ldg(reinterpret_cast<const long long*>(p) + e);
    return __ldg(reinterpret_cast<const int*>(p) + e);
}
// gather 4 halves (uint2) -> float4
__device__ __forceinline__ float4 gather_h4(const __half* msg, int row, int c) {
    uint2 u = __ldg(reinterpret_cast<const uint2*>(msg + (size_t)row * HDIM) + c);
    __half2 h0 = *reinterpret_cast<__half2*>(&u.x);
    __half2 h1 = *reinterpret_cast<__half2*>(&u.y);
    float2 f0 = __half22float2(h0);
    float2 f1 = __half22float2(h1);
    return make_float4(f0.x, f0.y, f1.x, f1.y);
}

// ---------------- zero counters + index width probe (fused) ----------------
__global__ __launch_bounds__(256) void zero_counts_kernel(const int* __restrict__ src32,
                                                          const int* __restrict__ dst32,
                                                          int n, int E) {
    int i = blockIdx.x * blockDim.x + threadIdx.x;
    if (i < n) { g_cnt_in[i] = 0; g_cnt_out[i] = 0; }
    if (i == 0) {
        int m = E < 256 ? E : 256;
        int is64 = 1;
        for (int k = 0; k < m; k++) {
            if (src32[2 * k + 1] != 0 || dst32[2 * k + 1] != 0) { is64 = 0; break; }
        }
        g_is64 = is64;
    }
}

// ---------------- weight pre-conversion ----------------
__global__ __launch_bounds__(256) void wconv_kernel(const float* __restrict__ W1,
                                                    const float* __restrict__ W2) {
    int i = blockIdx.x * blockDim.x + threadIdx.x;
    if (i < FDIM * HDIM) {
        unsigned short h, l;
        {
            int k = i >> 6, n = i & 63;
            bf16split(__ldg(&W1[i]), h, l);
            g_w1ht[n * FDIM + k] = h;
            g_w1lt[n * FDIM + k] = l;
        }
        {
            int k = i >> 9, n = i & 511;
            bf16split(__ldg(&W2[i]), h, l);
            g_w2ht[n * HDIM + k] = h;
            g_w2lt[n * HDIM + k] = l;
        }
    }
}

// ---------------- graph build ----------------
__global__ __launch_bounds__(256) void hist_kernel(const void* __restrict__ src,
                                                   const void* __restrict__ dst, int E) {
    int e = blockIdx.x * blockDim.x + threadIdx.x;
    if (e < E) {
        int is64 = g_is64;
        atomicAdd(&g_cnt_out[load_idx(src, e, is64)], 1);
        atomicAdd(&g_cnt_in[load_idx(dst, e, is64)], 1);
    }
}
__global__ __launch_bounds__(256) void scan1_kernel(int n) {
    __shared__ int sh[256];
    int tid = threadIdx.x;
    int base = blockIdx.x * 1024 + tid * 4;
    int v[4];
#pragma unroll
    for (int k = 0; k < 4; k++) v[k] = (base + k < n) ? g_cnt_in[base + k] : 0;
    int t = v[0] + v[1] + v[2] + v[3];
    sh[tid] = t;
    __syncthreads();
    for (int off = 1; off < 256; off <<= 1) {
        int x = (tid >= off) ? sh[tid - off] : 0;
        __syncthreads();
        sh[tid] += x;
        __syncthreads();
    }
    int run = sh[tid] - t;
#pragma unroll
    for (int k = 0; k < 4; k++) {
        if (base + k < n) g_row_start[base + k] = run;
        run += v[k];
    }
    if (tid == 255) g_bsum[blockIdx.x] = sh[255];
}
__global__ void scan2_kernel(int nb) {
    __shared__ int sh[256];
    int t = threadIdx.x;
    int v = (t < nb) ? g_bsum[t] : 0;
    sh[t] = v;
    __syncthreads();
    for (int off = 1; off < 256; off <<= 1) {
        int x = (t >= off) ? sh[t - off] : 0;
        __syncthreads();
        sh[t] += x;
        __syncthreads();
    }
    if (t < nb) g_bsum[t] = sh[t] - v;
}
__global__ __launch_bounds__(256) void scan3_kernel(int n, int E) {
    int i = blockIdx.x * blockDim.x + threadIdx.x;
    if (i < n) {
        int v = g_row_start[i] + g_bsum[i >> 10];
        g_row_start[i] = v;
        g_cursor[i] = v;
        g_norm_src[i] = rsqrtf(fmaxf((float)g_cnt_out[i], 1.0f));
        g_norm_dst[i] = rsqrtf(fmaxf((float)g_cnt_in[i], 1.0f));
    }
    if (i == 0) g_row_start[n] = E;
}
__global__ __launch_bounds__(256) void fill_kernel(const void* __restrict__ src,
                                                   const void* __restrict__ dst, int E) {
    int e = blockIdx.x * blockDim.x + threadIdx.x;
    if (e < E) {
        int is64 = g_is64;
        int s = load_idx(src, e, is64);
        int d = load_idx(dst, e, is64);
        int pos = atomicAdd(&g_cursor[d], 1);
        g_esrc[pos] = s;
    }
}

// ---------------- agg0: hs = relu((sum ns[sa]*x1g[sa]) * nd) * ns  (fp16 in/out) ----------------
__global__ __launch_bounds__(256) void agg0_kernel(const __half* __restrict__ msg,
                                                   __half* __restrict__ outh16, int n) {
    int node = blockIdx.x * 16 + (threadIdx.x >> 4);
    int c = threadIdx.x & 15;
    if (node >= n) return;
    int j = g_row_start[node];
    int s1 = g_row_start[node + 1];
    float4 acc = make_float4(0.f, 0.f, 0.f, 0.f);
    for (; j + 1 < s1; j += 2) {
        int sa = __ldg(&g_esrc[j]);
        int sb = __ldg(&g_esrc[j + 1]);
        float4 va = gather_h4(msg, sa, c);
        float4 vb = gather_h4(msg, sb, c);
        float na = __ldg(&g_norm_src[sa]);
        float nb = __ldg(&g_norm_src[sb]);
        acc.x = fmaf(va.x, na, acc.x); acc.y = fmaf(va.y, na, acc.y);
        acc.z = fmaf(va.z, na, acc.z); acc.w = fmaf(va.w, na, acc.w);
        acc.x = fmaf(vb.x, nb, acc.x); acc.y = fmaf(vb.y, nb, acc.y);
        acc.z = fmaf(vb.z, nb, acc.z); acc.w = fmaf(vb.w, nb, acc.w);
    }
    if (j < s1) {
        int sa = __ldg(&g_esrc[j]);
        float4 va = gather_h4(msg, sa, c);
        float na = __ldg(&g_norm_src[sa]);
        acc.x = fmaf(va.x, na, acc.x); acc.y = fmaf(va.y, na, acc.y);
        acc.z = fmaf(va.z, na, acc.z); acc.w = fmaf(va.w, na, acc.w);
    }
    float nd = g_norm_dst[node];
    float ns = g_norm_src[node];
    float4 o;
    o.x = fmaxf(acc.x * nd, 0.f) * ns;
    o.y = fmaxf(acc.y * nd, 0.f) * ns;
    o.z = fmaxf(acc.z * nd, 0.f) * ns;
    o.w = fmaxf(acc.w * nd, 0.f) * ns;
    __half2 p0 = __floats2half2_rn(o.x, o.y);
    __half2 p1 = __floats2half2_rn(o.z, o.w);
    uint2 u = make_uint2(reinterpret_cast<uint32_t&>(p0), reinterpret_cast<uint32_t&>(p1));
    reinterpret_cast<uint2*>(outh16 + (size_t)node * HDIM)[c] = u;
}

// ---------------- agg1: a2 = (sum hs[sa]) * nd -> bf16 hi/lo split ----------------
__global__ __launch_bounds__(256) void agg1_kernel(const __half* __restrict__ msg,
                                                   unsigned short* __restrict__ outh,
                                                   unsigned short* __restrict__ outl, int n) {
    int node = blockIdx.x * 16 + (threadIdx.x >> 4);
    int c = threadIdx.x & 15;
    if (node >= n) return;
    int j = g_row_start[node];
    int s1 = g_row_start[node + 1];
    float4 acc = make_float4(0.f, 0.f, 0.f, 0.f);
    for (; j + 1 < s1; j += 2) {
        int sa = __ldg(&g_esrc[j]);
        int sb = __ldg(&g_esrc[j + 1]);
        float4 va = gather_h4(msg, sa, c);
        float4 vb = gather_h4(msg, sb, c);
        acc.x += va.x; acc.y += va.y; acc.z += va.z; acc.w += va.w;
        acc.x += vb.x; acc.y += vb.y; acc.z += vb.z; acc.w += vb.w;
    }
    if (j < s1) {
        int sa = __ldg(&g_esrc[j]);
        float4 va = gather_h4(msg, sa, c);
        acc.x += va.x; acc.y += va.y; acc.z += va.z; acc.w += va.w;
    }
    float nd = g_norm_dst[node];
    uint32_t h01, l01, h23, l23;
    split2(acc.x * nd, acc.y * nd, h01, l01);
    split2(acc.z * nd, acc.w * nd, h23, l23);
    size_t off = ((size_t)node * HDIM + c * 4) >> 2;
    reinterpret_cast<uint2*>(outh)[off] = make_uint2(h01, h23);
    reinterpret_cast<uint2*>(outl)[off] = make_uint2(l01, l23);
}

// ---------------- GEMM1: x1g[M,64](fp16) = A(fp32)[M,512] @ W1 ----------------
#define AST 40
__global__ __launch_bounds__(256) void gemm1_kernel(const float* __restrict__ A,
                                                    const unsigned short* __restrict__ Bth,
                                                    const unsigned short* __restrict__ Btl,
                                                    __half* __restrict__ C, int M) {
    __shared__ __align__(16) unsigned short sAh[128 * AST];
    __shared__ __align__(16) unsigned short sAl[128 * AST];
    __shared__ __align__(16) unsigned short sBh[64 * AST];
    __shared__ __align__(16) unsigned short sBl[64 * AST];

    const int tid = threadIdx.x;
    const int wid = tid >> 5, lid = tid & 31;
    const int wm = wid & 3, wn = wid >> 2;
    const int block_m = blockIdx.x * 128;

    float acc[2][4][4];
#pragma unroll
    for (int i = 0; i < 2; i++)
#pragma unroll
        for (int j = 0; j < 4; j++)
#pragma unroll
            for (int q = 0; q < 4; q++) acc[i][j][q] = 0.f;

    const uint32_t aH = smem_to_u32(sAh);
    const uint32_t aL = smem_to_u32(sAl);
    const uint32_t bH = smem_to_u32(sBh);
    const uint32_t bL = smem_to_u32(sBl);

    const int b_n = tid >> 2, b_k8 = (tid & 3) * 8;
    for (int k0 = 0; k0 < FDIM; k0 += 32) {
#pragma unroll
        for (int it = 0; it < 4; it++) {
            int f = it * 256 + tid;
            int r = f >> 3, c4 = f & 7;
            int gr = block_m + r;
            float4 v = make_float4(0.f, 0.f, 0.f, 0.f);
            if (gr < M)
                v = __ldg(reinterpret_cast<const float4*>(A + (size_t)gr * FDIM + k0 + c4 * 4));
            uint32_t h01, l01, h23, l23;
            split2(v.x, v.y, h01, l01);
            split2(v.z, v.w, h23, l23);
            *reinterpret_cast<uint2*>(&sAh[r * AST + c4 * 4]) = make_uint2(h01, h23);
            *reinterpret_cast<uint2*>(&sAl[r * AST + c4 * 4]) = make_uint2(l01, l23);
        }
        {
            const size_t go = (size_t)b_n * FDIM + k0 + b_k8;
            uint4 vh = __ldg(reinterpret_cast<const uint4*>(Bth + go));
            uint4 vl = __ldg(reinterpret_cast<const uint4*>(Btl + go));
            *reinterpret_cast<uint4*>(&sBh[b_n * AST + b_k8]) = vh;
            *reinterpret_cast<uint4*>(&sBl[b_n * AST + b_k8]) = vl;
        }
        __syncthreads();

#pragma unroll
        for (int ks = 0; ks < 32; ks += 16) {
            uint32_t ah[2][4], al[2][4], bh[4][2], bl[4][2];
#pragma unroll
            for (int mf = 0; mf < 2; mf++) {
                uint32_t rowA = wm * 32 + mf * 16 + (lid & 15);
                uint32_t off = (rowA * AST + ks + (lid >> 4) * 8) * 2;
                ldsm4(ah[mf], aH + off);
                ldsm4(al[mf], aL + off);
            }
#pragma unroll
            for (int p = 0; p < 2; p++) {
                uint32_t nrow = wn * 32 + p * 16 + ((lid >> 4) & 1) * 8 + (lid & 7);
                uint32_t off = (nrow * AST + ks + ((lid >> 3) & 1) * 8) * 2;
                uint32_t r[4];
                ldsm4(r, bH + off);
                bh[2 * p][0] = r[0]; bh[2 * p][1] = r[1];
                bh[2 * p + 1][0] = r[2]; bh[2 * p + 1][1] = r[3];
                ldsm4(r, bL + off);
                bl[2 * p][0] = r[0]; bl[2 * p][1] = r[1];
                bl[2 * p + 1][0] = r[2]; bl[2 * p + 1][1] = r[3];
            }
#pragma unroll
            for (int mf = 0; mf < 2; mf++)
#pragma unroll
                for (int nf = 0; nf < 4; nf++) {
                    mma_bf16(acc[mf][nf], ah[mf], bh[nf]);
                    mma_bf16(acc[mf][nf], ah[mf], bl[nf]);
                    mma_bf16(acc[mf][nf], al[mf], bh[nf]);
                }
        }
        __syncthreads();
    }

    int lrow = lid >> 2, lcol = (lid & 3) * 2;
#pragma unroll
    for (int mf = 0; mf < 2; mf++)
#pragma unroll
        for (int half = 0; half < 2; half++) {
            int row = block_m + wm * 32 + mf * 16 + lrow + half * 8;
            if (row < M) {
#pragma unroll
                for (int nf = 0; nf < 4; nf++) {
                    int col = wn * 32 + nf * 8 + lcol;
                    __half2 o = __floats2half2_rn(acc[mf][nf][half * 2],
                                                  acc[mf][nf][half * 2 + 1]);
                    *reinterpret_cast<__half2*>(C + (size_t)row * HDIM + col) = o;
                }
            }
        }
}

// ---------------- GEMM2: C[M,512] = A(pre-split bf16)[M,64] @ W2 ----------------
#define AST2 72
#define G2_SMEM (2 * 128 * AST2 * 2 + 2 * 64 * AST2 * 2)
__global__ __launch_bounds__(256) void gemm2_kernel(const unsigned short* __restrict__ Ah,
                                                    const unsigned short* __restrict__ Al,
                                                    const unsigned short* __restrict__ Bth,
                                                    const unsigned short* __restrict__ Btl,
                                                    float* __restrict__ C, int M) {
    extern __shared__ __align__(16) unsigned short dyn[];
    unsigned short* sAh = dyn;
    unsigned short* sAl = sAh + 128 * AST2;
    unsigned short* sBh = sAl + 128 * AST2;
    unsigned short* sBl = sBh + 64 * AST2;

    const int tid = threadIdx.x;
    const int wid = tid >> 5, lid = tid & 31;
    const int wm = wid & 3, wn = wid >> 2;
    const int block_m = blockIdx.x * 128;

    const uint32_t aH = smem_to_u32(sAh);
    const uint32_t aL = smem_to_u32(sAl);
    const uint32_t bH = smem_to_u32(sBh);
    const uint32_t bL = smem_to_u32(sBl);

#pragma unroll
    for (int it = 0; it < 4; it++) {
        int u = it * 256 + tid;
        int r = u >> 3, q8 = (u & 7) * 8;
        int gr = block_m + r;
        uint4 vh = make_uint4(0, 0, 0, 0), vl = make_uint4(0, 0, 0, 0);
        if (gr < M) {
            size_t go = (size_t)gr * HDIM + q8;
            vh = __ldg(reinterpret_cast<const uint4*>(Ah + go));
            vl = __ldg(reinterpret_cast<const uint4*>(Al + go));
        }
        *reinterpret_cast<uint4*>(&sAh[r * AST2 + q8]) = vh;
        *reinterpret_cast<uint4*>(&sAl[r * AST2 + q8]) = vl;
    }

    int lrow = lid >> 2, lcol = (lid & 3) * 2;

    for (int nt = 0; nt < FDIM / 64; nt++) {
        const int n0 = nt * 64;
        __syncthreads();
#pragma unroll
        for (int it = 0; it < 2; it++) {
            int u = it * 256 + tid;
            int r = u >> 3, q8 = (u & 7) * 8;
            size_t go = (size_t)(n0 + r) * HDIM + q8;
            uint4 vh = __ldg(reinterpret_cast<const uint4*>(Bth + go));
            uint4 vl = __ldg(reinterpret_cast<const uint4*>(Btl + go));
            *reinterpret_cast<uint4*>(&sBh[r * AST2 + q8]) = vh;
            *reinterpret_cast<uint4*>(&sBl[r * AST2 + q8]) = vl;
        }
        __syncthreads();

        float acc[2][4][4];
#pragma unroll
        for (int i = 0; i < 2; i++)
#pragma unroll
            for (int j = 0; j < 4; j++)
#pragma unroll
                for (int q = 0; q < 4; q++) acc[i][j][q] = 0.f;

#pragma unroll
        for (int ks = 0; ks < 64; ks += 16) {
            uint32_t ah[2][4], al[2][4], bh[4][2], bl[4][2];
#pragma unroll
            for (int mf = 0; mf < 2; mf++) {
                uint32_t rowA = wm * 32 + mf * 16 + (lid & 15);
                uint32_t off = (rowA * AST2 + ks + (lid >> 4) * 8) * 2;
                ldsm4(ah[mf], aH + off);
                ldsm4(al[mf], aL + off);
            }
#pragma unroll
            for (int p = 0; p < 2; p++) {
                uint32_t nrow = wn * 32 + p * 16 + ((lid >> 4) & 1) * 8 + (lid & 7);
                uint32_t off = (nrow * AST2 + ks + ((lid >> 3) & 1) * 8) * 2;
                uint32_t r[4];
                ldsm4(r, bH + off);
                bh[2 * p][0] = r[0]; bh[2 * p][1] = r[1];
                bh[2 * p + 1][0] = r[2]; bh[2 * p + 1][1] = r[3];
                ldsm4(r, bL + off);
                bl[2 * p][0] = r[0]; bl[2 * p][1] = r[1];
                bl[2 * p + 1][0] = r[2]; bl[2 * p + 1][1] = r[3];
            }
#pragma unroll
            for (int mf = 0; mf < 2; mf++)
#pragma unroll
                for (int nf = 0; nf < 4; nf++) {
                    mma_bf16(acc[mf][nf], ah[mf], bh[nf]);
                    mma_bf16(acc[mf][nf], ah[mf], bl[nf]);
                    mma_bf16(acc[mf][nf], al[mf], bh[nf]);
                }
        }

#pragma unroll
        for (int mf = 0; mf < 2; mf++)
#pragma unroll
            for (int half = 0; half < 2; half++) {
                int row = block_m + wm * 32 + mf * 16 + lrow + half * 8;
                if (row < M) {
#pragma unroll
                    for (int nf = 0; nf < 4; nf++) {
                        int col = n0 + wn * 32 + nf * 8 + lcol;
                        float2 o = make_float2(acc[mf][nf][half * 2],
                                               acc[mf][nf][half * 2 + 1]);
                        *reinterpret_cast<float2*>(C + (size_t)row * FDIM + col) = o;
                    }
                }
            }
    }
}

// ---------------- streams/events (created once) ----------------
static cudaStream_t g_s2;
static cudaEvent_t g_evF, g_evJ;
static struct StreamInit {
    StreamInit() {
        cudaStreamCreateWithFlags(&g_s2, cudaStreamNonBlocking);
        cudaEventCreateWithFlags(&g_evF, cudaEventDisableTiming);
        cudaEventCreateWithFlags(&g_evJ, cudaEventDisableTiming);
    }
} g_stream_init;

// ---------------- launch ----------------
extern "C" void kernel_launch(void* const* d_in, const int* in_sizes, int n_in,
                              void* d_out, int out_size) {
    const float* features = (const float*)d_in[0];
    const void* src = d_in[1];
    const void* dst = d_in[2];
    const float* W1 = (const float*)d_in[3];
    const float* W2 = (const float*)d_in[4];
    float* out = (float*)d_out;

    const int N = N_NODES;
    const int E = in_sizes[1];

    __half *p_x1g, *p_hs;
    unsigned short *p_a2h, *p_a2l, *p_w1ht, *p_w1lt, *p_w2ht, *p_w2lt;
    cudaGetSymbolAddress((void**)&p_x1g, g_x1g);
    cudaGetSymbolAddress((void**)&p_hs, g_hs);
    cudaGetSymbolAddress((void**)&p_a2h, g_a2h);
    cudaGetSymbolAddress((void**)&p_a2l, g_a2l);
    cudaGetSymbolAddress((void**)&p_w1ht, g_w1ht);
    cudaGetSymbolAddress((void**)&p_w1lt, g_w1lt);
    cudaGetSymbolAddress((void**)&p_w2ht, g_w2ht);
    cudaGetSymbolAddress((void**)&p_w2lt, g_w2lt);

    cudaFuncSetAttribute(gemm2_kernel, cudaFuncAttributeMaxDynamicSharedMemorySize, G2_SMEM);

    const int nb_scan = (N + 1023) / 1024;
    const int mtiles = (N + 127) / 128;

    // ---- fork: wconv + GEMM1 on side stream (R12 schedule) ----
    cudaEventRecord(g_evF, 0);
    cudaStreamWaitEvent(g_s2, g_evF, 0);
    wconv_kernel<<<(FDIM * HDIM + 255) / 256, 256, 0, g_s2>>>(W1, W2);
    gemm1_kernel<<<mtiles, 256, 0, g_s2>>>(features, p_w1ht, p_w1lt, p_x1g, N);
    cudaEventRecord(g_evJ, g_s2);

    // ---- main stream: graph build ----
    zero_counts_kernel<<<(N + 255) / 256, 256>>>((const int*)src, (const int*)dst, N, E);
    hist_kernel<<<(E + 255) / 256, 256>>>(src, dst, E);
    scan1_kernel<<<nb_scan, 256>>>(N);
    scan2_kernel<<<1, 256>>>(nb_scan);
    scan3_kernel<<<(N + 255) / 256, 256>>>(N, E);
    fill_kernel<<<(E + 255) / 256, 256>>>(src, dst, E);

    // ---- join, then tail ----
    cudaStreamWaitEvent(0, g_evJ, 0);
    agg0_kernel<<<(N + 15) / 16, 256>>>(p_x1g, p_hs, N);
    agg1_kernel<<<(N + 15) / 16, 256>>>(p_hs, p_a2h, p_a2l, N);
    gemm2_kernel<<<mtiles, 256, G2_SMEM>>>(p_a2h, p_a2l, p_w2ht, p_w2lt, out, N);
}

// round 16
// speedup vs baseline: 1.2636x; 1.0618x over previous
#include <cuda_runtime.h>
#include <cuda_bf16.h>
#include <cuda_fp16.h>
#include <cstdint>

#define N_NODES 100000
#define E_MAX   1600000
#define FDIM 512
#define HDIM 64

// ---------------- scratch ----------------
__device__ __align__(128) __half g_x1g[(size_t)N_NODES * HDIM];  // X@W1 (UNscaled, fp16)
__device__ __align__(128) __half g_hs[(size_t)N_NODES * HDIM];   // relu(agg1*nd)*ns (fp16)
__device__ __align__(128) unsigned short g_a2h[(size_t)N_NODES * HDIM];  // a2 fp16 hi
__device__ __align__(128) unsigned short g_a2l[(size_t)N_NODES * HDIM];  // a2 fp16 lo
__device__ __align__(128) float g_norm_src[N_NODES];
__device__ __align__(128) float g_norm_dst[N_NODES];
// W1^T [64][512] fp16, W2^T [512][64] fp16 (single precision pass for W)
__device__ __align__(128) __half g_w1f[HDIM * FDIM];
__device__ __align__(128) __half g_w2f[FDIM * HDIM];
__device__ int g_cnt_in[N_NODES];
__device__ int g_cnt_out[N_NODES];
__device__ int g_row_start[N_NODES + 1];
__device__ int g_cursor[N_NODES];
__device__ int g_esrc[E_MAX];
__device__ int g_bsum[256];
__device__ int g_is64;

// ---------------- helpers ----------------
__device__ __forceinline__ uint32_t smem_to_u32(const void* p) {
    uint32_t a;
    asm("{ .reg .u64 t; cvta.to.shared.u64 t, %1; cvt.u32.u64 %0, t; }" : "=r"(a) : "l"(p));
    return a;
}
__device__ __forceinline__ void ldsm4(uint32_t* r, uint32_t addr) {
    asm volatile("ldmatrix.sync.aligned.m8n8.x4.shared.b16 {%0,%1,%2,%3}, [%4];"
                 : "=r"(r[0]), "=r"(r[1]), "=r"(r[2]), "=r"(r[3]) : "r"(addr));
}
__device__ __forceinline__ void mma_f16(float* c, const uint32_t* a, const uint32_t* b) {
    asm volatile(
        "mma.sync.aligned.m16n8k16.row.col.f32.f16.f16.f32 "
        "{%0,%1,%2,%3}, {%4,%5,%6,%7}, {%8,%9}, {%0,%1,%2,%3};"
        : "+f"(c[0]), "+f"(c[1]), "+f"(c[2]), "+f"(c[3])
        : "r"(a[0]), "r"(a[1]), "r"(a[2]), "r"(a[3]), "r"(b[0]), "r"(b[1]));
}
// paired fp32 -> fp16 hi/lo split
__device__ __forceinline__ void split2h(float x, float y, uint32_t& h2, uint32_t& l2) {
    __half2 hh = __floats2half2_rn(x, y);
    float2 f = __half22float2(hh);
    __half2 ll = __floats2half2_rn(x - f.x, y - f.y);
    h2 = reinterpret_cast<uint32_t&>(hh);
    l2 = reinterpret_cast<uint32_t&>(ll);
}
__device__ __forceinline__ int load_idx(const void* p, int e, int is64) {
    if (is64) return (int)__ldg(reinterpret_cast<const long long*>(p) + e);
    return __ldg(reinterpret_cast<const int*>(p) + e);
}
__device__ __forceinline__ float4 gather_h4(const __half* msg, int row, int c) {
    uint2 u = __ldg(reinterpret_cast<const uint2*>(msg + (size_t)row * HDIM) + c);
    __half2 h0 = *reinterpret_cast<__half2*>(&u.x);
    __half2 h1 = *reinterpret_cast<__half2*>(&u.y);
    float2 f0 = __half22float2(h0);
    float2 f1 = __half22float2(h1);
    return make_float4(f0.x, f0.y, f1.x, f1.y);
}

// ---------------- zero counters + index width probe (fused) ----------------
__global__ __launch_bounds__(256) void zero_counts_kernel(const int* __restrict__ src32,
                                                          const int* __restrict__ dst32,
                                                          int n, int E) {
    int i = blockIdx.x * blockDim.x + threadIdx.x;
    if (i < n) { g_cnt_in[i] = 0; g_cnt_out[i] = 0; }
    if (i == 0) {
        int m = E < 256 ? E : 256;
        int is64 = 1;
        for (int k = 0; k < m; k++) {
            if (src32[2 * k + 1] != 0 || dst32[2 * k + 1] != 0) { is64 = 0; break; }
        }
        g_is64 = is64;
    }
}

// ---------------- weight pre-conversion: transpose + fp16 ----------------
__global__ __launch_bounds__(256) void wconv_kernel(const float* __restrict__ W1,
                                                    const float* __restrict__ W2) {
    int i = blockIdx.x * blockDim.x + threadIdx.x;
    if (i < FDIM * HDIM) {
        {
            int k = i >> 6, n = i & 63;
            g_w1f[n * FDIM + k] = __float2half(__ldg(&W1[i]));
        }
        {
            int k = i >> 9, n = i & 511;
            g_w2f[n * HDIM + k] = __float2half(__ldg(&W2[i]));
        }
    }
}

// ---------------- graph build ----------------
__global__ __launch_bounds__(256) void hist_kernel(const void* __restrict__ src,
                                                   const void* __restrict__ dst, int E) {
    int e = blockIdx.x * blockDim.x + threadIdx.x;
    if (e < E) {
        int is64 = g_is64;
        atomicAdd(&g_cnt_out[load_idx(src, e, is64)], 1);
        atomicAdd(&g_cnt_in[load_idx(dst, e, is64)], 1);
    }
}
__global__ __launch_bounds__(256) void scan1_kernel(int n) {
    __shared__ int sh[256];
    int tid = threadIdx.x;
    int base = blockIdx.x * 1024 + tid * 4;
    int v[4];
#pragma unroll
    for (int k = 0; k < 4; k++) v[k] = (base + k < n) ? g_cnt_in[base + k] : 0;
    int t = v[0] + v[1] + v[2] + v[3];
    sh[tid] = t;
    __syncthreads();
    for (int off = 1; off < 256; off <<= 1) {
        int x = (tid >= off) ? sh[tid - off] : 0;
        __syncthreads();
        sh[tid] += x;
        __syncthreads();
    }
    int run = sh[tid] - t;
#pragma unroll
    for (int k = 0; k < 4; k++) {
        if (base + k < n) g_row_start[base + k] = run;
        run += v[k];
    }
    if (tid == 255) g_bsum[blockIdx.x] = sh[255];
}
__global__ void scan2_kernel(int nb) {
    __shared__ int sh[256];
    int t = threadIdx.x;
    int v = (t < nb) ? g_bsum[t] : 0;
    sh[t] = v;
    __syncthreads();
    for (int off = 1; off < 256; off <<= 1) {
        int x = (t >= off) ? sh[t - off] : 0;
        __syncthreads();
        sh[t] += x;
        __syncthreads();
    }
    if (t < nb) g_bsum[t] = sh[t] - v;
}
__global__ __launch_bounds__(256) void scan3_kernel(int n, int E) {
    int i = blockIdx.x * blockDim.x + threadIdx.x;
    if (i < n) {
        int v = g_row_start[i] + g_bsum[i >> 10];
        g_row_start[i] = v;
        g_cursor[i] = v;
        g_norm_src[i] = rsqrtf(fmaxf((float)g_cnt_out[i], 1.0f));
        g_norm_dst[i] = rsqrtf(fmaxf((float)g_cnt_in[i], 1.0f));
    }
    if (i == 0) g_row_start[n] = E;
}
__global__ __launch_bounds__(256) void fill_kernel(const void* __restrict__ src,
                                                   const void* __restrict__ dst, int E) {
    int e = blockIdx.x * blockDim.x + threadIdx.x;
    if (e < E) {
        int is64 = g_is64;
        int s = load_idx(src, e, is64);
        int d = load_idx(dst, e, is64);
        int pos = atomicAdd(&g_cursor[d], 1);
        g_esrc[pos] = s;
    }
}

// ---------------- agg0: hs = relu((sum ns[sa]*x1g[sa]) * nd) * ns (fp16 in/out) ----------------
__global__ __launch_bounds__(256) void agg0_kernel(const __half* __restrict__ msg,
                                                   __half* __restrict__ outh16, int n) {
    int node = blockIdx.x * 16 + (threadIdx.x >> 4);
    int c = threadIdx.x & 15;
    if (node >= n) return;
    int j = g_row_start[node];
    int s1 = g_row_start[node + 1];
    float4 acc = make_float4(0.f, 0.f, 0.f, 0.f);
    for (; j + 1 < s1; j += 2) {
        int sa = __ldg(&g_esrc[j]);
        int sb = __ldg(&g_esrc[j + 1]);
        float4 va = gather_h4(msg, sa, c);
        float4 vb = gather_h4(msg, sb, c);
        float na = __ldg(&g_norm_src[sa]);
        float nb = __ldg(&g_norm_src[sb]);
        acc.x = fmaf(va.x, na, acc.x); acc.y = fmaf(va.y, na, acc.y);
        acc.z = fmaf(va.z, na, acc.z); acc.w = fmaf(va.w, na, acc.w);
        acc.x = fmaf(vb.x, nb, acc.x); acc.y = fmaf(vb.y, nb, acc.y);
        acc.z = fmaf(vb.z, nb, acc.z); acc.w = fmaf(vb.w, nb, acc.w);
    }
    if (j < s1) {
        int sa = __ldg(&g_esrc[j]);
        float4 va = gather_h4(msg, sa, c);
        float na = __ldg(&g_norm_src[sa]);
        acc.x = fmaf(va.x, na, acc.x); acc.y = fmaf(va.y, na, acc.y);
        acc.z = fmaf(va.z, na, acc.z); acc.w = fmaf(va.w, na, acc.w);
    }
    float nd = g_norm_dst[node];
    float ns = g_norm_src[node];
    float4 o;
    o.x = fmaxf(acc.x * nd, 0.f) * ns;
    o.y = fmaxf(acc.y * nd, 0.f) * ns;
    o.z = fmaxf(acc.z * nd, 0.f) * ns;
    o.w = fmaxf(acc.w * nd, 0.f) * ns;
    __half2 p0 = __floats2half2_rn(o.x, o.y);
    __half2 p1 = __floats2half2_rn(o.z, o.w);
    uint2 u = make_uint2(reinterpret_cast<uint32_t&>(p0), reinterpret_cast<uint32_t&>(p1));
    reinterpret_cast<uint2*>(outh16 + (size_t)node * HDIM)[c] = u;
}

// ---------------- agg1: a2 = (sum hs[sa]) * nd -> fp16 hi/lo split ----------------
__global__ __launch_bounds__(256) void agg1_kernel(const __half* __restrict__ msg,
                                                   unsigned short* __restrict__ outh,
                                                   unsigned short* __restrict__ outl, int n) {
    int node = blockIdx.x * 16 + (threadIdx.x >> 4);
    int c = threadIdx.x & 15;
    if (node >= n) return;
    int j = g_row_start[node];
    int s1 = g_row_start[node + 1];
    float4 acc = make_float4(0.f, 0.f, 0.f, 0.f);
    for (; j + 1 < s1; j += 2) {
        int sa = __ldg(&g_esrc[j]);
        int sb = __ldg(&g_esrc[j + 1]);
        float4 va = gather_h4(msg, sa, c);
        float4 vb = gather_h4(msg, sb, c);
        acc.x += va.x; acc.y += va.y; acc.z += va.z; acc.w += va.w;
        acc.x += vb.x; acc.y += vb.y; acc.z += vb.z; acc.w += vb.w;
    }
    if (j < s1) {
        int sa = __ldg(&g_esrc[j]);
        float4 va = gather_h4(msg, sa, c);
        acc.x += va.x; acc.y += va.y; acc.z += va.z; acc.w += va.w;
    }
    float nd = g_norm_dst[node];
    uint32_t h01, l01, h23, l23;
    split2h(acc.x * nd, acc.y * nd, h01, l01);
    split2h(acc.z * nd, acc.w * nd, h23, l23);
    size_t off = ((size_t)node * HDIM + c * 4) >> 2;
    reinterpret_cast<uint2*>(outh)[off] = make_uint2(h01, h23);
    reinterpret_cast<uint2*>(outl)[off] = make_uint2(l01, l23);
}

// ---------------- GEMM1: x1g[M,64](fp16) = A(fp32)[M,512] @ W1 ----------------
// A fp16 hi/lo split (2-pass), W single fp16. CTA 128x64, 8 warps.
#define AST 40
__global__ __launch_bounds__(256) void gemm1_kernel(const float* __restrict__ A,
                                                    const __half* __restrict__ Bt,
                                                    __half* __restrict__ C, int M) {
    __shared__ __align__(16) unsigned short sAh[128 * AST];
    __shared__ __align__(16) unsigned short sAl[128 * AST];
    __shared__ __align__(16) unsigned short sB[64 * AST];

    const int tid = threadIdx.x;
    const int wid = tid >> 5, lid = tid & 31;
    const int wm = wid & 3, wn = wid >> 2;
    const int block_m = blockIdx.x * 128;

    float acc[2][4][4];
#pragma unroll
    for (int i = 0; i < 2; i++)
#pragma unroll
        for (int j = 0; j < 4; j++)
#pragma unroll
            for (int q = 0; q < 4; q++) acc[i][j][q] = 0.f;

    const uint32_t aH = smem_to_u32(sAh);
    const uint32_t aL = smem_to_u32(sAl);
    const uint32_t bB = smem_to_u32(sB);

    const int b_n = tid >> 2, b_k8 = (tid & 3) * 8;
    for (int k0 = 0; k0 < FDIM; k0 += 32) {
        // ---- A: 128x32 fp32 -> fp16 hi/lo ----
#pragma unroll
        for (int it = 0; it < 4; it++) {
            int f = it * 256 + tid;
            int r = f >> 3, c4 = f & 7;
            int gr = block_m + r;
            float4 v = make_float4(0.f, 0.f, 0.f, 0.f);
            if (gr < M)
                v = __ldg(reinterpret_cast<const float4*>(A + (size_t)gr * FDIM + k0 + c4 * 4));
            uint32_t h01, l01, h23, l23;
            split2h(v.x, v.y, h01, l01);
            split2h(v.z, v.w, h23, l23);
            *reinterpret_cast<uint2*>(&sAh[r * AST + c4 * 4]) = make_uint2(h01, h23);
            *reinterpret_cast<uint2*>(&sAl[r * AST + c4 * 4]) = make_uint2(l01, l23);
        }
        // ---- B: pure uint4 copy of fp16 weights ----
        {
            const size_t go = (size_t)b_n * FDIM + k0 + b_k8;
            uint4 vb = __ldg(reinterpret_cast<const uint4*>(Bt + go));
            *reinterpret_cast<uint4*>(&sB[b_n * AST + b_k8]) = vb;
        }
        __syncthreads();

#pragma unroll
        for (int ks = 0; ks < 32; ks += 16) {
            uint32_t ah[2][4], al[2][4], bb[4][2];
#pragma unroll
            for (int mf = 0; mf < 2; mf++) {
                uint32_t rowA = wm * 32 + mf * 16 + (lid & 15);
                uint32_t off = (rowA * AST + ks + (lid >> 4) * 8) * 2;
                ldsm4(ah[mf], aH + off);
                ldsm4(al[mf], aL + off);
            }
#pragma unroll
            for (int p = 0; p < 2; p++) {
                uint32_t nrow = wn * 32 + p * 16 + ((lid >> 4) & 1) * 8 + (lid & 7);
                uint32_t off = (nrow * AST + ks + ((lid >> 3) & 1) * 8) * 2;
                uint32_t r[4];
                ldsm4(r, bB + off);
                bb[2 * p][0] = r[0]; bb[2 * p][1] = r[1];
                bb[2 * p + 1][0] = r[2]; bb[2 * p + 1][1] = r[3];
            }
#pragma unroll
            for (int mf = 0; mf < 2; mf++)
#pragma unroll
                for (int nf = 0; nf < 4; nf++) {
                    mma_f16(acc[mf][nf], ah[mf], bb[nf]);
                    mma_f16(acc[mf][nf], al[mf], bb[nf]);
                }
        }
        __syncthreads();
    }

    int lrow = lid >> 2, lcol = (lid & 3) * 2;
#pragma unroll
    for (int mf = 0; mf < 2; mf++)
#pragma unroll
        for (int half = 0; half < 2; half++) {
            int row = block_m + wm * 32 + mf * 16 + lrow + half * 8;
            if (row < M) {
#pragma unroll
                for (int nf = 0; nf < 4; nf++) {
                    int col = wn * 32 + nf * 8 + lcol;
                    __half2 o = __floats2half2_rn(acc[mf][nf][half * 2],
                                                  acc[mf][nf][half * 2 + 1]);
                    *reinterpret_cast<__half2*>(C + (size_t)row * HDIM + col) = o;
                }
            }
        }
}

// ---------------- GEMM2: C[M,512] = A(fp16 hi/lo)[M,64] @ W2(fp16), 2-pass ----------------
#define AST2 72
#define G2_SMEM ((2 * 128 + 64) * AST2 * 2)
__global__ __launch_bounds__(256) void gemm2_kernel(const unsigned short* __restrict__ Ah,
                                                    const unsigned short* __restrict__ Al,
                                                    const __half* __restrict__ Bt,
                                                    float* __restrict__ C, int M) {
    extern __shared__ __align__(16) unsigned short dyn[];
    unsigned short* sAh = dyn;
    unsigned short* sAl = sAh + 128 * AST2;
    unsigned short* sB = sAl + 128 * AST2;

    const int tid = threadIdx.x;
    const int wid = tid >> 5, lid = tid & 31;
    const int wm = wid & 3, wn = wid >> 2;
    const int block_m = blockIdx.x * 128;

    const uint32_t aH = smem_to_u32(sAh);
    const uint32_t aL = smem_to_u32(sAl);
    const uint32_t bB = smem_to_u32(sB);

    // ---- load A once (pure copies) ----
#pragma unroll
    for (int it = 0; it < 4; it++) {
        int u = it * 256 + tid;
        int r = u >> 3, q8 = (u & 7) * 8;
        int gr = block_m + r;
        uint4 vh = make_uint4(0, 0, 0, 0), vl = make_uint4(0, 0, 0, 0);
        if (gr < M) {
            size_t go = (size_t)gr * HDIM + q8;
            vh = __ldg(reinterpret_cast<const uint4*>(Ah + go));
            vl = __ldg(reinterpret_cast<const uint4*>(Al + go));
        }
        *reinterpret_cast<uint4*>(&sAh[r * AST2 + q8]) = vh;
        *reinterpret_cast<uint4*>(&sAl[r * AST2 + q8]) = vl;
    }

    int lrow = lid >> 2, lcol = (lid & 3) * 2;

    for (int nt = 0; nt < FDIM / 64; nt++) {
        const int n0 = nt * 64;
        __syncthreads();
        // ---- B tile: 64 rows x 64 halfs = 512 uint4 ----
#pragma unroll
        for (int it = 0; it < 2; it++) {
            int u = it * 256 + tid;
            int r = u >> 3, q8 = (u & 7) * 8;
            size_t go = (size_t)(n0 + r) * HDIM + q8;
            uint4 vb = __ldg(reinterpret_cast<const uint4*>(Bt + go));
            *reinterpret_cast<uint4*>(&sB[r * AST2 + q8]) = vb;
        }
        __syncthreads();

        float acc[2][4][4];
#pragma unroll
        for (int i = 0; i < 2; i++)
#pragma unroll
            for (int j = 0; j < 4; j++)
#pragma unroll
                for (int q = 0; q < 4; q++) acc[i][j][q] = 0.f;

#pragma unroll
        for (int ks = 0; ks < 64; ks += 16) {
            uint32_t ah[2][4], al[2][4], bb[4][2];
#pragma unroll
            for (int mf = 0; mf < 2; mf++) {
                uint32_t rowA = wm * 32 + mf * 16 + (lid & 15);
                uint32_t off = (rowA * AST2 + ks + (lid >> 4) * 8) * 2;
                ldsm4(ah[mf], aH + off);
                ldsm4(al[mf], aL + off);
            }
#pragma unroll
            for (int p = 0; p < 2; p++) {
                uint32_t nrow = wn * 32 + p * 16 + ((lid >> 4) & 1) * 8 + (lid & 7);
                uint32_t off = (nrow * AST2 + ks + ((lid >> 3) & 1) * 8) * 2;
                uint32_t r[4];
                ldsm4(r, bB + off);
                bb[2 * p][0] = r[0]; bb[2 * p][1] = r[1];
                bb[2 * p + 1][0] = r[2]; bb[2 * p + 1][1] = r[3];
            }
#pragma unroll
            for (int mf = 0; mf < 2; mf++)
#pragma unroll
                for (int nf = 0; nf < 4; nf++) {
                    mma_f16(acc[mf][nf], ah[mf], bb[nf]);
                    mma_f16(acc[mf][nf], al[mf], bb[nf]);
                }
        }

#pragma unroll
        for (int mf = 0; mf < 2; mf++)
#pragma unroll
            for (int half = 0; half < 2; half++) {
                int row = block_m + wm * 32 + mf * 16 + lrow + half * 8;
                if (row < M) {
#pragma unroll
                    for (int nf = 0; nf < 4; nf++) {
                        int col = n0 + wn * 32 + nf * 8 + lcol;
                        float2 o = make_float2(acc[mf][nf][half * 2],
                                               acc[mf][nf][half * 2 + 1]);
                        *reinterpret_cast<float2*>(C + (size_t)row * FDIM + col) = o;
                    }
                }
            }
    }
}

// ---------------- streams/events (created once) ----------------
static cudaStream_t g_s2;
static cudaEvent_t g_evF, g_evJ;
static struct StreamInit {
    StreamInit() {
        cudaStreamCreateWithFlags(&g_s2, cudaStreamNonBlocking);
        cudaEventCreateWithFlags(&g_evF, cudaEventDisableTiming);
        cudaEventCreateWithFlags(&g_evJ, cudaEventDisableTiming);
    }
} g_stream_init;

// ---------------- launch ----------------
extern "C" void kernel_launch(void* const* d_in, const int* in_sizes, int n_in,
                              void* d_out, int out_size) {
    const float* features = (const float*)d_in[0];
    const void* src = d_in[1];
    const void* dst = d_in[2];
    const float* W1 = (const float*)d_in[3];
    const float* W2 = (const float*)d_in[4];
    float* out = (float*)d_out;

    const int N = N_NODES;
    const int E = in_sizes[1];

    __half *p_x1g, *p_hs, *p_w1f, *p_w2f;
    unsigned short *p_a2h, *p_a2l;
    cudaGetSymbolAddress((void**)&p_x1g, g_x1g);
    cudaGetSymbolAddress((void**)&p_hs, g_hs);
    cudaGetSymbolAddress((void**)&p_a2h, g_a2h);
    cudaGetSymbolAddress((void**)&p_a2l, g_a2l);
    cudaGetSymbolAddress((void**)&p_w1f, g_w1f);
    cudaGetSymbolAddress((void**)&p_w2f, g_w2f);

    cudaFuncSetAttribute(gemm2_kernel, cudaFuncAttributeMaxDynamicSharedMemorySize, G2_SMEM);

    const int nb_scan = (N + 1023) / 1024;
    const int mtiles = (N + 127) / 128;

    // ---- fork: wconv + GEMM1 on side stream ----
    cudaEventRecord(g_evF, 0);
    cudaStreamWaitEvent(g_s2, g_evF, 0);
    wconv_kernel<<<(FDIM * HDIM + 255) / 256, 256, 0, g_s2>>>(W1, W2);
    gemm1_kernel<<<mtiles, 256, 0, g_s2>>>(features, p_w1f, p_x1g, N);
    cudaEventRecord(g_evJ, g_s2);

    // ---- main stream: graph build ----
    zero_counts_kernel<<<(N + 255) / 256, 256>>>((const int*)src, (const int*)dst, N, E);
    hist_kernel<<<(E + 255) / 256, 256>>>(src, dst, E);
    scan1_kernel<<<nb_scan, 256>>>(N);
    scan2_kernel<<<1, 256>>>(nb_scan);
    scan3_kernel<<<(N + 255) / 256, 256>>>(N, E);
    fill_kernel<<<(E + 255) / 256, 256>>>(src, dst, E);

    // ---- join, then tail ----
    cudaStreamWaitEvent(0, g_evJ, 0);
    agg0_kernel<<<(N + 15) / 16, 256>>>(p_x1g, p_hs, N);
    agg1_kernel<<<(N + 15) / 16, 256>>>(p_hs, p_a2h, p_a2l, N);
    gemm2_kernel<<<mtiles, 256, G2_SMEM>>>(p_a2h, p_a2l, p_w2f, out, N);
}

// round 17
// speedup vs baseline: 1.2731x; 1.0075x over previous
#include <cuda_runtime.h>
#include <cuda_bf16.h>
#include <cuda_fp16.h>
#include <cstdint>

#define N_NODES 100000
#define E_MAX   1600000
#define FDIM 512
#define HDIM 64

// ---------------- scratch ----------------
__device__ __align__(128) __half g_x1g[(size_t)N_NODES * HDIM];  // X@W1 (UNscaled, fp16)
__device__ __align__(128) __half g_hs[(size_t)N_NODES * HDIM];   // relu(agg1*nd)*ns (fp16)
__device__ __align__(128) unsigned short g_a2h[(size_t)N_NODES * HDIM];  // a2 fp16 hi
__device__ __align__(128) unsigned short g_a2l[(size_t)N_NODES * HDIM];  // a2 fp16 lo
__device__ __align__(128) float g_norm_src[N_NODES];
__device__ __align__(128) float g_norm_dst[N_NODES];
__device__ __align__(128) __half g_w1f[HDIM * FDIM];
__device__ __align__(128) __half g_w2f[FDIM * HDIM];
__device__ int g_cnt_in[N_NODES];
__device__ int g_cnt_out[N_NODES];
__device__ int g_row_start[N_NODES + 1];
__device__ int g_cursor[N_NODES];
__device__ int g_esrc[E_MAX];
__device__ int g_bsum[256];
__device__ int g_is64;

// ---------------- helpers ----------------
__device__ __forceinline__ uint32_t smem_to_u32(const void* p) {
    uint32_t a;
    asm("{ .reg .u64 t; cvta.to.shared.u64 t, %1; cvt.u32.u64 %0, t; }" : "=r"(a) : "l"(p));
    return a;
}
__device__ __forceinline__ void ldsm4(uint32_t* r, uint32_t addr) {
    asm volatile("ldmatrix.sync.aligned.m8n8.x4.shared.b16 {%0,%1,%2,%3}, [%4];"
                 : "=r"(r[0]), "=r"(r[1]), "=r"(r[2]), "=r"(r[3]) : "r"(addr));
}
__device__ __forceinline__ void mma_f16(float* c, const uint32_t* a, const uint32_t* b) {
    asm volatile(
        "mma.sync.aligned.m16n8k16.row.col.f32.f16.f16.f32 "
        "{%0,%1,%2,%3}, {%4,%5,%6,%7}, {%8,%9}, {%0,%1,%2,%3};"
        : "+f"(c[0]), "+f"(c[1]), "+f"(c[2]), "+f"(c[3])
        : "r"(a[0]), "r"(a[1]), "r"(a[2]), "r"(a[3]), "r"(b[0]), "r"(b[1]));
}
__device__ __forceinline__ void split2h(float x, float y, uint32_t& h2, uint32_t& l2) {
    __half2 hh = __floats2half2_rn(x, y);
    float2 f = __half22float2(hh);
    __half2 ll = __floats2half2_rn(x - f.x, y - f.y);
    h2 = reinterpret_cast<uint32_t&>(hh);
    l2 = reinterpret_cast<uint32_t&>(ll);
}
__device__ __forceinline__ int load_idx(const void* p, int e, int is64) {
    if (is64) return (int)__ldg(reinterpret_cast<const long long*>(p) + e);
    return __ldg(reinterpret_cast<const int*>(p) + e);
}
__device__ __forceinline__ float4 gather_h4(const __half* msg, int row, int c) {
    uint2 u = __ldg(reinterpret_cast<const uint2*>(msg + (size_t)row * HDIM) + c);
    __half2 h0 = *reinterpret_cast<__half2*>(&u.x);
    __half2 h1 = *reinterpret_cast<__half2*>(&u.y);
    float2 f0 = __half22float2(h0);
    float2 f1 = __half22float2(h1);
    return make_float4(f0.x, f0.y, f1.x, f1.y);
}

// ---------------- zero counters + index width probe (fused) ----------------
__global__ __launch_bounds__(256) void zero_counts_kernel(const int* __restrict__ src32,
                                                          const int* __restrict__ dst32,
                                                          int n, int E) {
    int i = blockIdx.x * blockDim.x + threadIdx.x;
    if (i < n) { g_cnt_in[i] = 0; g_cnt_out[i] = 0; }
    if (i == 0) {
        int m = E < 256 ? E : 256;
        int is64 = 1;
        for (int k = 0; k < m; k++) {
            if (src32[2 * k + 1] != 0 || dst32[2 * k + 1] != 0) { is64 = 0; break; }
        }
        g_is64 = is64;
    }
}

// ---------------- weight pre-conversion: transpose + fp16 ----------------
__global__ __launch_bounds__(256) void wconv_kernel(const float* __restrict__ W1,
                                                    const float* __restrict__ W2) {
    int i = blockIdx.x * blockDim.x + threadIdx.x;
    if (i < FDIM * HDIM) {
        {
            int k = i >> 6, n = i & 63;
            g_w1f[n * FDIM + k] = __float2half(__ldg(&W1[i]));
        }
        {
            int k = i >> 9, n = i & 511;
            g_w2f[n * HDIM + k] = __float2half(__ldg(&W2[i]));
        }
    }
}

// ---------------- graph build ----------------
__global__ __launch_bounds__(256) void hist_kernel(const void* __restrict__ src,
                                                   const void* __restrict__ dst, int E) {
    int e = blockIdx.x * blockDim.x + threadIdx.x;
    if (e < E) {
        int is64 = g_is64;
        atomicAdd(&g_cnt_out[load_idx(src, e, is64)], 1);
        atomicAdd(&g_cnt_in[load_idx(dst, e, is64)], 1);
    }
}
__global__ __launch_bounds__(256) void scan1_kernel(int n) {
    __shared__ int sh[256];
    int tid = threadIdx.x;
    int base = blockIdx.x * 1024 + tid * 4;
    int v[4];
#pragma unroll
    for (int k = 0; k < 4; k++) v[k] = (base + k < n) ? g_cnt_in[base + k] : 0;
    int t = v[0] + v[1] + v[2] + v[3];
    sh[tid] = t;
    __syncthreads();
    for (int off = 1; off < 256; off <<= 1) {
        int x = (tid >= off) ? sh[tid - off] : 0;
        __syncthreads();
        sh[tid] += x;
        __syncthreads();
    }
    int run = sh[tid] - t;
#pragma unroll
    for (int k = 0; k < 4; k++) {
        if (base + k < n) g_row_start[base + k] = run;
        run += v[k];
    }
    if (tid == 255) g_bsum[blockIdx.x] = sh[255];
}
__global__ void scan2_kernel(int nb) {
    __shared__ int sh[256];
    int t = threadIdx.x;
    int v = (t < nb) ? g_bsum[t] : 0;
    sh[t] = v;
    __syncthreads();
    for (int off = 1; off < 256; off <<= 1) {
        int x = (t >= off) ? sh[t - off] : 0;
        __syncthreads();
        sh[t] += x;
        __syncthreads();
    }
    if (t < nb) g_bsum[t] = sh[t] - v;
}
__global__ __launch_bounds__(256) void scan3_kernel(int n, int E) {
    int i = blockIdx.x * blockDim.x + threadIdx.x;
    if (i < n) {
        int v = g_row_start[i] + g_bsum[i >> 10];
        g_row_start[i] = v;
        g_cursor[i] = v;
        g_norm_src[i] = rsqrtf(fmaxf((float)g_cnt_out[i], 1.0f));
        g_norm_dst[i] = rsqrtf(fmaxf((float)g_cnt_in[i], 1.0f));
    }
    if (i == 0) g_row_start[n] = E;
}
__global__ __launch_bounds__(256) void fill_kernel(const void* __restrict__ src,
                                                   const void* __restrict__ dst, int E) {
    int e = blockIdx.x * blockDim.x + threadIdx.x;
    if (e < E) {
        int is64 = g_is64;
        int s = load_idx(src, e, is64);
        int d = load_idx(dst, e, is64);
        int pos = atomicAdd(&g_cursor[d], 1);
        g_esrc[pos] = s;
    }
}

// ---------------- agg0: hs = relu((sum ns[sa]*x1g[sa]) * nd) * ns (fp16 in/out) ----------------
__global__ __launch_bounds__(256) void agg0_kernel(const __half* __restrict__ msg,
                                                   __half* __restrict__ outh16, int n) {
    int node = blockIdx.x * 16 + (threadIdx.x >> 4);
    int c = threadIdx.x & 15;
    if (node >= n) return;
    int j = g_row_start[node];
    int s1 = g_row_start[node + 1];
    float4 acc = make_float4(0.f, 0.f, 0.f, 0.f);
    for (; j + 1 < s1; j += 2) {
        int sa = __ldg(&g_esrc[j]);
        int sb = __ldg(&g_esrc[j + 1]);
        float4 va = gather_h4(msg, sa, c);
        float4 vb = gather_h4(msg, sb, c);
        float na = __ldg(&g_norm_src[sa]);
        float nb = __ldg(&g_norm_src[sb]);
        acc.x = fmaf(va.x, na, acc.x); acc.y = fmaf(va.y, na, acc.y);
        acc.z = fmaf(va.z, na, acc.z); acc.w = fmaf(va.w, na, acc.w);
        acc.x = fmaf(vb.x, nb, acc.x); acc.y = fmaf(vb.y, nb, acc.y);
        acc.z = fmaf(vb.z, nb, acc.z); acc.w = fmaf(vb.w, nb, acc.w);
    }
    if (j < s1) {
        int sa = __ldg(&g_esrc[j]);
        float4 va = gather_h4(msg, sa, c);
        float na = __ldg(&g_norm_src[sa]);
        acc.x = fmaf(va.x, na, acc.x); acc.y = fmaf(va.y, na, acc.y);
        acc.z = fmaf(va.z, na, acc.z); acc.w = fmaf(va.w, na, acc.w);
    }
    float nd = g_norm_dst[node];
    float ns = g_norm_src[node];
    float4 o;
    o.x = fmaxf(acc.x * nd, 0.f) * ns;
    o.y = fmaxf(acc.y * nd, 0.f) * ns;
    o.z = fmaxf(acc.z * nd, 0.f) * ns;
    o.w = fmaxf(acc.w * nd, 0.f) * ns;
    __half2 p0 = __floats2half2_rn(o.x, o.y);
    __half2 p1 = __floats2half2_rn(o.z, o.w);
    uint2 u = make_uint2(reinterpret_cast<uint32_t&>(p0), reinterpret_cast<uint32_t&>(p1));
    reinterpret_cast<uint2*>(outh16 + (size_t)node * HDIM)[c] = u;
}

// ---------------- agg1: a2 = (sum hs[sa]) * nd -> fp16 hi/lo (node range [n0, n1)) ----------------
__global__ __launch_bounds__(256) void agg1_kernel(const __half* __restrict__ msg,
                                                   unsigned short* __restrict__ outh,
                                                   unsigned short* __restrict__ outl,
                                                   int n0, int n1) {
    int node = n0 + blockIdx.x * 16 + (threadIdx.x >> 4);
    int c = threadIdx.x & 15;
    if (node >= n1) return;
    int j = g_row_start[node];
    int s1 = g_row_start[node + 1];
    float4 acc = make_float4(0.f, 0.f, 0.f, 0.f);
    for (; j + 1 < s1; j += 2) {
        int sa = __ldg(&g_esrc[j]);
        int sb = __ldg(&g_esrc[j + 1]);
        float4 va = gather_h4(msg, sa, c);
        float4 vb = gather_h4(msg, sb, c);
        acc.x += va.x; acc.y += va.y; acc.z += va.z; acc.w += va.w;
        acc.x += vb.x; acc.y += vb.y; acc.z += vb.z; acc.w += vb.w;
    }
    if (j < s1) {
        int sa = __ldg(&g_esrc[j]);
        float4 va = gather_h4(msg, sa, c);
        acc.x += va.x; acc.y += va.y; acc.z += va.z; acc.w += va.w;
    }
    float nd = g_norm_dst[node];
    uint32_t h01, l01, h23, l23;
    split2h(acc.x * nd, acc.y * nd, h01, l01);
    split2h(acc.z * nd, acc.w * nd, h23, l23);
    size_t off = ((size_t)node * HDIM + c * 4) >> 2;
    reinterpret_cast<uint2*>(outh)[off] = make_uint2(h01, h23);
    reinterpret_cast<uint2*>(outl)[off] = make_uint2(l01, l23);
}

// ---------------- GEMM1: x1g[M,64](fp16) = A(fp32)[M,512] @ W1 ----------------
#define AST 40
__global__ __launch_bounds__(256) void gemm1_kernel(const float* __restrict__ A,
                                                    const __half* __restrict__ Bt,
                                                    __half* __restrict__ C, int M) {
    __shared__ __align__(16) unsigned short sAh[128 * AST];
    __shared__ __align__(16) unsigned short sAl[128 * AST];
    __shared__ __align__(16) unsigned short sB[64 * AST];

    const int tid = threadIdx.x;
    const int wid = tid >> 5, lid = tid & 31;
    const int wm = wid & 3, wn = wid >> 2;
    const int block_m = blockIdx.x * 128;

    float acc[2][4][4];
#pragma unroll
    for (int i = 0; i < 2; i++)
#pragma unroll
        for (int j = 0; j < 4; j++)
#pragma unroll
            for (int q = 0; q < 4; q++) acc[i][j][q] = 0.f;

    const uint32_t aH = smem_to_u32(sAh);
    const uint32_t aL = smem_to_u32(sAl);
    const uint32_t bB = smem_to_u32(sB);

    const int b_n = tid >> 2, b_k8 = (tid & 3) * 8;
    for (int k0 = 0; k0 < FDIM; k0 += 32) {
#pragma unroll
        for (int it = 0; it < 4; it++) {
            int f = it * 256 + tid;
            int r = f >> 3, c4 = f & 7;
            int gr = block_m + r;
            float4 v = make_float4(0.f, 0.f, 0.f, 0.f);
            if (gr < M)
                v = __ldg(reinterpret_cast<const float4*>(A + (size_t)gr * FDIM + k0 + c4 * 4));
            uint32_t h01, l01, h23, l23;
            split2h(v.x, v.y, h01, l01);
            split2h(v.z, v.w, h23, l23);
            *reinterpret_cast<uint2*>(&sAh[r * AST + c4 * 4]) = make_uint2(h01, h23);
            *reinterpret_cast<uint2*>(&sAl[r * AST + c4 * 4]) = make_uint2(l01, l23);
        }
        {
            const size_t go = (size_t)b_n * FDIM + k0 + b_k8;
            uint4 vb = __ldg(reinterpret_cast<const uint4*>(Bt + go));
            *reinterpret_cast<uint4*>(&sB[b_n * AST + b_k8]) = vb;
        }
        __syncthreads();

#pragma unroll
        for (int ks = 0; ks < 32; ks += 16) {
            uint32_t ah[2][4], al[2][4], bb[4][2];
#pragma unroll
            for (int mf = 0; mf < 2; mf++) {
                uint32_t rowA = wm * 32 + mf * 16 + (lid & 15);
                uint32_t off = (rowA * AST + ks + (lid >> 4) * 8) * 2;
                ldsm4(ah[mf], aH + off);
                ldsm4(al[mf], aL + off);
            }
#pragma unroll
            for (int p = 0; p < 2; p++) {
                uint32_t nrow = wn * 32 + p * 16 + ((lid >> 4) & 1) * 8 + (lid & 7);
                uint32_t off = (nrow * AST + ks + ((lid >> 3) & 1) * 8) * 2;
                uint32_t r[4];
                ldsm4(r, bB + off);
                bb[2 * p][0] = r[0]; bb[2 * p][1] = r[1];
                bb[2 * p + 1][0] = r[2]; bb[2 * p + 1][1] = r[3];
            }
#pragma unroll
            for (int mf = 0; mf < 2; mf++)
#pragma unroll
                for (int nf = 0; nf < 4; nf++) {
                    mma_f16(acc[mf][nf], ah[mf], bb[nf]);
                    mma_f16(acc[mf][nf], al[mf], bb[nf]);
                }
        }
        __syncthreads();
    }

    int lrow = lid >> 2, lcol = (lid & 3) * 2;
#pragma unroll
    for (int mf = 0; mf < 2; mf++)
#pragma unroll
        for (int half = 0; half < 2; half++) {
            int row = block_m + wm * 32 + mf * 16 + lrow + half * 8;
            if (row < M) {
#pragma unroll
                for (int nf = 0; nf < 4; nf++) {
                    int col = wn * 32 + nf * 8 + lcol;
                    __half2 o = __floats2half2_rn(acc[mf][nf][half * 2],
                                                  acc[mf][nf][half * 2 + 1]);
                    *reinterpret_cast<__half2*>(C + (size_t)row * HDIM + col) = o;
                }
            }
        }
}

// ---------------- GEMM2: C[M,512] = A(fp16 hi/lo)[M,64] @ W2(fp16); m-tile range ----------------
#define AST2 72
#define G2_SMEM ((2 * 128 + 64) * AST2 * 2)
__global__ __launch_bounds__(256) void gemm2_kernel(const unsigned short* __restrict__ Ah,
                                                    const unsigned short* __restrict__ Al,
                                                    const __half* __restrict__ Bt,
                                                    float* __restrict__ C, int M, int m0) {
    extern __shared__ __align__(16) unsigned short dyn[];
    unsigned short* sAh = dyn;
    unsigned short* sAl = sAh + 128 * AST2;
    unsigned short* sB = sAl + 128 * AST2;

    const int tid = threadIdx.x;
    const int wid = tid >> 5, lid = tid & 31;
    const int wm = wid & 3, wn = wid >> 2;
    const int block_m = (m0 + blockIdx.x) * 128;

    const uint32_t aH = smem_to_u32(sAh);
    const uint32_t aL = smem_to_u32(sAl);
    const uint32_t bB = smem_to_u32(sB);

#pragma unroll
    for (int it = 0; it < 4; it++) {
        int u = it * 256 + tid;
        int r = u >> 3, q8 = (u & 7) * 8;
        int gr = block_m + r;
        uint4 vh = make_uint4(0, 0, 0, 0), vl = make_uint4(0, 0, 0, 0);
        if (gr < M) {
            size_t go = (size_t)gr * HDIM + q8;
            vh = __ldg(reinterpret_cast<const uint4*>(Ah + go));
            vl = __ldg(reinterpret_cast<const uint4*>(Al + go));
        }
        *reinterpret_cast<uint4*>(&sAh[r * AST2 + q8]) = vh;
        *reinterpret_cast<uint4*>(&sAl[r * AST2 + q8]) = vl;
    }

    int lrow = lid >> 2, lcol = (lid & 3) * 2;

    for (int nt = 0; nt < FDIM / 64; nt++) {
        const int n0 = nt * 64;
        __syncthreads();
#pragma unroll
        for (int it = 0; it < 2; it++) {
            int u = it * 256 + tid;
            int r = u >> 3, q8 = (u & 7) * 8;
            size_t go = (size_t)(n0 + r) * HDIM + q8;
            uint4 vb = __ldg(reinterpret_cast<const uint4*>(Bt + go));
            *reinterpret_cast<uint4*>(&sB[r * AST2 + q8]) = vb;
        }
        __syncthreads();

        float acc[2][4][4];
#pragma unroll
        for (int i = 0; i < 2; i++)
#pragma unroll
            for (int j = 0; j < 4; j++)
#pragma unroll
                for (int q = 0; q < 4; q++) acc[i][j][q] = 0.f;

#pragma unroll
        for (int ks = 0; ks < 64; ks += 16) {
            uint32_t ah[2][4], al[2][4], bb[4][2];
#pragma unroll
            for (int mf = 0; mf < 2; mf++) {
                uint32_t rowA = wm * 32 + mf * 16 + (lid & 15);
                uint32_t off = (rowA * AST2 + ks + (lid >> 4) * 8) * 2;
                ldsm4(ah[mf], aH + off);
                ldsm4(al[mf], aL + off);
            }
#pragma unroll
            for (int p = 0; p < 2; p++) {
                uint32_t nrow = wn * 32 + p * 16 + ((lid >> 4) & 1) * 8 + (lid & 7);
                uint32_t off = (nrow * AST2 + ks + ((lid >> 3) & 1) * 8) * 2;
                uint32_t r[4];
                ldsm4(r, bB + off);
                bb[2 * p][0] = r[0]; bb[2 * p][1] = r[1];
                bb[2 * p + 1][0] = r[2]; bb[2 * p + 1][1] = r[3];
            }
#pragma unroll
            for (int mf = 0; mf < 2; mf++)
#pragma unroll
                for (int nf = 0; nf < 4; nf++) {
                    mma_f16(acc[mf][nf], ah[mf], bb[nf]);
                    mma_f16(acc[mf][nf], al[mf], bb[nf]);
                }
        }

#pragma unroll
        for (int mf = 0; mf < 2; mf++)
#pragma unroll
            for (int half = 0; half < 2; half++) {
                int row = block_m + wm * 32 + mf * 16 + lrow + half * 8;
                if (row < M) {
#pragma unroll
                    for (int nf = 0; nf < 4; nf++) {
                        int col = n0 + wn * 32 + nf * 8 + lcol;
                        float2 o = make_float2(acc[mf][nf][half * 2],
                                               acc[mf][nf][half * 2 + 1]);
                        *reinterpret_cast<float2*>(C + (size_t)row * FDIM + col) = o;
                    }
                }
            }
    }
}

// ---------------- streams/events (created once) ----------------
static cudaStream_t g_s2;
static cudaEvent_t g_evF, g_evJ, g_evA0, g_evA1;
static struct StreamInit {
    StreamInit() {
        cudaStreamCreateWithFlags(&g_s2, cudaStreamNonBlocking);
        cudaEventCreateWithFlags(&g_evF, cudaEventDisableTiming);
        cudaEventCreateWithFlags(&g_evJ, cudaEventDisableTiming);
        cudaEventCreateWithFlags(&g_evA0, cudaEventDisableTiming);
        cudaEventCreateWithFlags(&g_evA1, cudaEventDisableTiming);
    }
} g_stream_init;

// ---------------- launch ----------------
extern "C" void kernel_launch(void* const* d_in, const int* in_sizes, int n_in,
                              void* d_out, int out_size) {
    const float* features = (const float*)d_in[0];
    const void* src = d_in[1];
    const void* dst = d_in[2];
    const float* W1 = (const float*)d_in[3];
    const float* W2 = (const float*)d_in[4];
    float* out = (float*)d_out;

    const int N = N_NODES;
    const int E = in_sizes[1];

    __half *p_x1g, *p_hs, *p_w1f, *p_w2f;
    unsigned short *p_a2h, *p_a2l;
    cudaGetSymbolAddress((void**)&p_x1g, g_x1g);
    cudaGetSymbolAddress((void**)&p_hs, g_hs);
    cudaGetSymbolAddress((void**)&p_a2h, g_a2h);
    cudaGetSymbolAddress((void**)&p_a2l, g_a2l);
    cudaGetSymbolAddress((void**)&p_w1f, g_w1f);
    cudaGetSymbolAddress((void**)&p_w2f, g_w2f);

    cudaFuncSetAttribute(gemm2_kernel, cudaFuncAttributeMaxDynamicSharedMemorySize, G2_SMEM);

    const int nb_scan = (N + 1023) / 1024;
    const int mtiles = (N + 127) / 128;
    // split tail in two halves at an m-tile boundary
    const int mt_half = mtiles / 2;
    const int n_half = mt_half * 128;   // node split point

    // ---- fork: wconv + GEMM1 on side stream ----
    cudaEventRecord(g_evF, 0);
    cudaStreamWaitEvent(g_s2, g_evF, 0);
    wconv_kernel<<<(FDIM * HDIM + 255) / 256, 256, 0, g_s2>>>(W1, W2);
    gemm1_kernel<<<mtiles, 256, 0, g_s2>>>(features, p_w1f, p_x1g, N);
    cudaEventRecord(g_evJ, g_s2);

    // ---- main stream: graph build ----
    zero_counts_kernel<<<(N + 255) / 256, 256>>>((const int*)src, (const int*)dst, N, E);
    hist_kernel<<<(E + 255) / 256, 256>>>(src, dst, E);
    scan1_kernel<<<nb_scan, 256>>>(N);
    scan2_kernel<<<1, 256>>>(nb_scan);
    scan3_kernel<<<(N + 255) / 256, 256>>>(N, E);
    fill_kernel<<<(E + 255) / 256, 256>>>(src, dst, E);

    // ---- join, then agg0 ----
    cudaStreamWaitEvent(0, g_evJ, 0);
    agg0_kernel<<<(N + 15) / 16, 256>>>(p_x1g, p_hs, N);
    cudaEventRecord(g_evA0, 0);

    // ---- pipelined tail: agg1 half1 on side stream || agg1 half0 + gemm2 half0 on main ----
    cudaStreamWaitEvent(g_s2, g_evA0, 0);
    {
        int cnt1 = N - n_half;
        agg1_kernel<<<(cnt1 + 15) / 16, 256, 0, g_s2>>>(p_hs, p_a2h, p_a2l, n_half, N);
        cudaEventRecord(g_evA1, g_s2);
    }
    agg1_kernel<<<(n_half + 15) / 16, 256>>>(p_hs, p_a2h, p_a2l, 0, n_half);
    gemm2_kernel<<<mt_half, 256, G2_SMEM>>>(p_a2h, p_a2l, p_w2f, out, N, 0);
    cudaStreamWaitEvent(0, g_evA1, 0);
    gemm2_kernel<<<mtiles - mt_half, 256, G2_SMEM>>>(p_a2h, p_a2l, p_w2f, out, N, mt_half);
}